// round 13
// baseline (speedup 1.0000x reference)
#include <cuda_runtime.h>
#include <math.h>
#include <stdint.h>

#define BSZ 2
#define SEQ 2048
#define HIDDEN 2048
#define NH 32
#define NKV 8
#define HD 64
#define NREP 4

// Scratch (static device arrays — no allocation).
__device__ float g_q[BSZ * NH * SEQ * HD];      // [b, h, s, d] tf32-rounded, pre-scaled 1/8
__device__ float g_k[BSZ * NKV * SEQ * HD];     // [b, kvh, s, d] tf32-rounded
__device__ float g_v[BSZ * NKV * HD * SEQ];     // [b, kvh, d, s] (TRANSPOSED) tf32-rounded
__device__ float g_attn[BSZ * SEQ * NH * HD];   // [b, s, h*d] tf32-rounded

__device__ float g_ht[BSZ * SEQ * HIDDEN];      // tf32-rounded hidden
__device__ float g_wqt[NH * HD * HIDDEN];       // [N,K] k-major, tf32-rounded
__device__ float g_wkt[NKV * HD * HIDDEN];
__device__ float g_wvt[NKV * HD * HIDDEN];
__device__ float g_wot[HIDDEN * NH * HD];       // [N=2048, K=2048]
__device__ float g_rope[SEQ * 64];              // [s][0:32 cos | 32:64 sin]

// ---------------------------------------------------------------------------
// Helpers
// ---------------------------------------------------------------------------
__device__ __forceinline__ float tf32r(float x) {
    unsigned u;
    asm("cvt.rna.tf32.f32 %0, %1;" : "=r"(u) : "f"(x));
    return __uint_as_float(u);
}
#define F2U __float_as_uint

__device__ __forceinline__ void mma8(float c[4],
                                     unsigned a0, unsigned a1, unsigned a2, unsigned a3,
                                     unsigned b0, unsigned b1) {
    asm volatile(
        "mma.sync.aligned.m16n8k8.row.col.f32.tf32.tf32.f32 "
        "{%0,%1,%2,%3}, {%4,%5,%6,%7}, {%8,%9}, {%0,%1,%2,%3};\n"
        : "+f"(c[0]), "+f"(c[1]), "+f"(c[2]), "+f"(c[3])
        : "r"(a0), "r"(a1), "r"(a2), "r"(a3), "r"(b0), "r"(b1));
}
__device__ __forceinline__ void ldsm4(unsigned& r0, unsigned& r1,
                                      unsigned& r2, unsigned& r3, uint32_t addr) {
    asm volatile("ldmatrix.sync.aligned.m8n8.x4.shared.b16 {%0,%1,%2,%3}, [%4];"
                 : "=r"(r0), "=r"(r1), "=r"(r2), "=r"(r3) : "r"(addr));
}

// ---------------------------------------------------------------------------
// Prologue: round hidden; merged transpose; RoPE cos/sin table
// ---------------------------------------------------------------------------
__global__ void round_tf32(const float* __restrict__ src, float* __restrict__ dst, int n4)
{
    for (int i = blockIdx.x * blockDim.x + threadIdx.x; i < n4; i += gridDim.x * blockDim.x) {
        float4 v = ((const float4*)src)[i];
        v.x = tf32r(v.x); v.y = tf32r(v.y); v.z = tf32r(v.z); v.w = tf32r(v.w);
        ((float4*)dst)[i] = v;
    }
}

__global__ void rope_fill()
{
    int idx = blockIdx.x * blockDim.x + threadIdx.x;   // 65536 total
    int s = idx >> 5, p = idx & 31;
    float inv = powf(10000.0f, -((float)(2 * p) / 64.0f));
    float ang = (float)s * inv;
    float c, si;
    sincosf(ang, &si, &c);
    g_rope[s * 64 + p] = c;
    g_rope[s * 64 + 32 + p] = si;
}

// Merged transpose: blockIdx.z selects (src,dst,Kd,Nd) segment.
// dst[n*Kd + k] = tf32r(src[k*Nd + n])
__global__ void transpose_all(const float* __restrict__ wq, const float* __restrict__ wk,
                              const float* __restrict__ wv, const float* __restrict__ wo)
{
    __shared__ float t[32][33];
    const float* src;
    float* dst;
    int Kd, Nd;
    int seg = blockIdx.z;
    if (seg == 0)      { src = wq; dst = g_wqt; Kd = HIDDEN;  Nd = NH * HD; }
    else if (seg == 1) { src = wk; dst = g_wkt; Kd = HIDDEN;  Nd = NKV * HD; }
    else if (seg == 2) { src = wv; dst = g_wvt; Kd = HIDDEN;  Nd = NKV * HD; }
    else               { src = wo; dst = g_wot; Kd = NH * HD; Nd = HIDDEN; }

    const int n0 = blockIdx.x * 32, k0 = blockIdx.y * 32;
    if (n0 >= Nd || k0 >= Kd) return;
    const int tx = threadIdx.x, ty = threadIdx.y;
#pragma unroll
    for (int i = 0; i < 4; i++)
        t[ty + i * 8][tx] = src[(size_t)(k0 + ty + i * 8) * Nd + n0 + tx];
    __syncthreads();
#pragma unroll
    for (int i = 0; i < 4; i++)
        dst[(size_t)(n0 + ty + i * 8) * Kd + k0 + tx] = tf32r(t[tx][ty + i * 8]);
}

// ---------------------------------------------------------------------------
// GEMM mainloop v4: as v3 but prefetch ISSUE hoisted to the top of the chunk
// (stage (kc+2)%3 == (kc-1)%3 is free once the top barrier passes) -> cover
// grows from ~1 chunk to ~2 chunks of compute.
// ---------------------------------------------------------------------------
#define STAGE_B 16384u
#define GEMM_SMEM (6 * 16384)

template<int WARPS_M>
__device__ __forceinline__ void gemm_mainloop3(
    const float* __restrict__ Ag, const float* __restrict__ Bg,
    int K, float (*acc)[4])
{
    extern __shared__ float smem[];
    constexpr int MT = 8 / WARPS_M;
    constexpr int NT = 2 * WARPS_M;
    constexpr int NPAIR = NT / 2;

    const int tid  = threadIdx.x;
    const int lane = tid & 31;
    const int warp = tid >> 5;
    const int wm   = warp % WARPS_M;
    const int wn   = warp / WARPS_M;

    const uint32_t sA = (uint32_t)__cvta_generic_to_shared(smem);
    const uint32_t sB = sA + 3 * STAGE_B;

    const int lrow = tid >> 3;
    const int lj   = tid & 7;
    const uint32_t wsw = (uint32_t)((lj ^ (lrow & 7)) << 4);

    const int frow = ((lane >> 3) & 1) * 8 + (lane & 7);
    const int fjb  = lane >> 4;
    const int axr  = frow & 7;
    const uint32_t arowb = (uint32_t)((wm * MT * 16 + frow) * 128);
    const int brow = (lane & 7) + ((lane >> 4) & 1) * 8;
    const int bjb  = (lane >> 3) & 1;
    const int bxr  = brow & 7;
    const uint32_t browb = (uint32_t)((wn * NT * 8 + brow) * 128);

#define ISSUE(kc, st) do {                                                           \
    _Pragma("unroll")                                                                \
    for (int i = 0; i < 4; i++) {                                                    \
        const int r = lrow + 32 * i;                                                 \
        const float* sa = Ag + (size_t)r * K + (kc) * 32 + lj * 4;                   \
        const uint32_t da = sA + (uint32_t)(st) * STAGE_B + (uint32_t)(r * 128) + wsw; \
        asm volatile("cp.async.cg.shared.global [%0], [%1], 16;" :: "r"(da), "l"(sa)); \
    }                                                                                \
    _Pragma("unroll")                                                                \
    for (int i = 0; i < 4; i++) {                                                    \
        const int r = lrow + 32 * i;                                                 \
        const float* sb = Bg + (size_t)r * K + (kc) * 32 + lj * 4;                   \
        const uint32_t db = sB + (uint32_t)(st) * STAGE_B + (uint32_t)(r * 128) + wsw; \
        asm volatile("cp.async.cg.shared.global [%0], [%1], 16;" :: "r"(db), "l"(sb)); \
    }                                                                                \
    asm volatile("cp.async.commit_group;");                                          \
} while (0)

    const int nkc = K >> 5;
    ISSUE(0, 0);
    ISSUE(1, 1);

    for (int kc = 0; kc < nkc; kc++) {
        if (kc < nkc - 1) asm volatile("cp.async.wait_group 1;");
        else              asm volatile("cp.async.wait_group 0;");
        __syncthreads();
        if (kc + 2 < nkc) ISSUE(kc + 2, (kc + 2) % 3);   // hoisted prefetch

        const int st = kc % 3;
        const uint32_t aS = sA + (uint32_t)st * STAGE_B;
        const uint32_t bS = sB + (uint32_t)st * STAGE_B;

#pragma unroll
        for (int ks = 0; ks < 4; ks++) {
            unsigned a[MT][4];
#pragma unroll
            for (int mt = 0; mt < MT; mt++)
                ldsm4(a[mt][0], a[mt][1], a[mt][2], a[mt][3],
                      aS + arowb + (uint32_t)(mt * 2048)
                         + (uint32_t)((((2 * ks + fjb) ^ axr)) << 4));
#pragma unroll
            for (int ntp = 0; ntp < NPAIR; ntp++) {
                unsigned b0, b1, b2, b3;
                ldsm4(b0, b1, b2, b3,
                      bS + browb + (uint32_t)(ntp * 2048)
                         + (uint32_t)((((2 * ks + bjb) ^ bxr)) << 4));
#pragma unroll
                for (int mt = 0; mt < MT; mt++) {
                    mma8(acc[mt * NT + 2 * ntp],     a[mt][0], a[mt][1], a[mt][2], a[mt][3], b0, b1);
                    mma8(acc[mt * NT + 2 * ntp + 1], a[mt][0], a[mt][1], a[mt][2], a[mt][3], b2, b3);
                }
            }
        }
    }
#undef ISSUE
}

// ---------------------------------------------------------------------------
// Fused QKV projection + RoPE epilogue (cos/sin from g_rope table).
// V is stored TRANSPOSED [b,kvh,d,s].
// ---------------------------------------------------------------------------
__global__ __launch_bounds__(256, 2)
void qkv_gemm()
{
    const int bx = blockIdx.x, by = blockIdx.y;
    const int tid = threadIdx.x;
    const int lane = tid & 31, warp = tid >> 5;
    const int wm = warp % 4, wn = warp / 4;
    const int q = lane & 3, g = lane >> 2;

    const float* W;
    float* Out;
    int cb, heads;
    bool rope;
    float oscale;
    if (bx < 16)      { W = g_wqt; Out = g_q; cb = bx * 128;        heads = NH;  rope = true;  oscale = 0.125f; }
    else if (bx < 20) { W = g_wkt; Out = g_k; cb = (bx - 16) * 128; heads = NKV; rope = true;  oscale = 1.0f; }
    else              { W = g_wvt; Out = g_v; cb = (bx - 20) * 128; heads = NKV; rope = false; oscale = 1.0f; }

    float acc[16][4];
#pragma unroll
    for (int i = 0; i < 16; i++)
#pragma unroll
        for (int j = 0; j < 4; j++) acc[i][j] = 0.0f;

    gemm_mainloop3<4>(g_ht + (size_t)(by * 128) * HIDDEN,
                      W + (size_t)cb * HIDDEN, HIDDEN, acc);

    if (rope) {
#pragma unroll
        for (int mt = 0; mt < 2; mt++) {
#pragma unroll
            for (int rh = 0; rh < 2; rh++) {
                const int m = by * 128 + wm * 32 + mt * 16 + g + rh * 8;
                const int ss = m & (SEQ - 1);
                const float* rp = g_rope + ss * 64;
#pragma unroll
                for (int ntp = 0; ntp < 4; ntp++) {
                    const int f = ntp * 8 + (q << 1);
                    const float2 cc = *(const float2*)(rp + f);
                    const float2 sn = *(const float2*)(rp + 32 + f);
                    {
                        const float x1 = acc[mt * 8 + ntp][rh * 2];
                        const float x2 = acc[mt * 8 + ntp + 4][rh * 2];
                        acc[mt * 8 + ntp][rh * 2]     = x1 * cc.x - x2 * sn.x;
                        acc[mt * 8 + ntp + 4][rh * 2] = x2 * cc.x + x1 * sn.x;
                    }
                    {
                        const float x1 = acc[mt * 8 + ntp][rh * 2 + 1];
                        const float x2 = acc[mt * 8 + ntp + 4][rh * 2 + 1];
                        acc[mt * 8 + ntp][rh * 2 + 1]     = x1 * cc.y - x2 * sn.y;
                        acc[mt * 8 + ntp + 4][rh * 2 + 1] = x2 * cc.y + x1 * sn.y;
                    }
                }
            }
        }
    }

#pragma unroll
    for (int mt = 0; mt < 2; mt++) {
        const int row = by * 128 + wm * 32 + mt * 16 + g;
#pragma unroll
        for (int nt = 0; nt < 8; nt++) {
            const int col = cb + wn * 64 + nt * 8 + (q << 1);
            const int hh = col / HD, dd = col & (HD - 1);
#pragma unroll
            for (int rh = 0; rh < 2; rh++) {
                const int m = row + rh * 8;
                const int bb = m >> 11, ss = m & (SEQ - 1);
                if (rope) {
                    float* p = Out + (((size_t)bb * heads + hh) * SEQ + ss) * HD + dd;
                    p[0] = tf32r(acc[mt * 8 + nt][rh * 2]     * oscale);
                    p[1] = tf32r(acc[mt * 8 + nt][rh * 2 + 1] * oscale);
                } else {
                    float* p = Out + (((size_t)bb * heads + hh) * HD + dd) * SEQ + ss;
                    p[0]   = tf32r(acc[mt * 8 + nt][rh * 2]);
                    p[SEQ] = tf32r(acc[mt * 8 + nt][rh * 2 + 1]);
                }
            }
        }
    }
}

// ---------------------------------------------------------------------------
// Output projection
// ---------------------------------------------------------------------------
__global__ __launch_bounds__(256, 2)
void gemm_o(float* __restrict__ C)
{
    const int bx = blockIdx.x, by = blockIdx.y;
    const int tid = threadIdx.x;
    const int lane = tid & 31, warp = tid >> 5;
    const int wm = warp % 2, wn = warp / 2;
    const int q = lane & 3, g = lane >> 2;

    float acc[16][4];
#pragma unroll
    for (int i = 0; i < 16; i++)
#pragma unroll
        for (int j = 0; j < 4; j++) acc[i][j] = 0.0f;

    gemm_mainloop3<2>(g_attn + (size_t)(by * 128) * HIDDEN,
                      g_wot + (size_t)(bx * 128) * HIDDEN, HIDDEN, acc);

#pragma unroll
    for (int mt = 0; mt < 4; mt++) {
        const int row = by * 128 + wm * 64 + mt * 16 + g;
#pragma unroll
        for (int nt = 0; nt < 4; nt++) {
            const int col = bx * 128 + wn * 32 + nt * 8 + (q << 1);
            *(float2*)(C + (size_t)row * HIDDEN + col) =
                make_float2(acc[mt * 4 + nt][0], acc[mt * 4 + nt][1]);
            *(float2*)(C + (size_t)(row + 8) * HIDDEN + col) =
                make_float2(acc[mt * 4 + nt][2], acc[mt * 4 + nt][3]);
        }
    }
}

// ---------------------------------------------------------------------------
// Flash attention: 64-row Q tiles, 4 warps, occ 3. DOUBLE-BUFFERED K:
// K(kt+1) issued right after the top K-wait -> cover = S+softmax+PV.
// P register-resident via shfl. V single-buffered (cover = S+softmax).
// In-flight trace (in-order completion): top wait_group 1 -> K(kt) done;
// after softmax wait_group 1 (tail 0) -> V(kt) done.
// ---------------------------------------------------------------------------
#define QSTR 68
#define KB_BYTES (64 * QSTR * 4)
#define FLASH_SMEM (64 * QSTR * 4 * 4)     // Qs + 2xK + V = 69632 B

__global__ __launch_bounds__(128, 3)
void flash_tf32(const float* __restrict__ Q, const float* __restrict__ K,
                const float* __restrict__ V, float* __restrict__ O)
{
    extern __shared__ float sm[];
    float* Qs = sm;                         // Q staging (dead after hoist)
    float* Ks = Qs + 64 * QSTR;             // 2 stages
    float* Vs = Ks + 2 * 64 * QSTR;

    const int qb   = gridDim.x - 1 - blockIdx.x;   // heavy blocks first
    const int h    = blockIdx.y;
    const int b    = blockIdx.z;
    const int tid  = threadIdx.x;
    const int lane = tid & 31;
    const int warp = tid >> 5;
    const int q    = lane & 3;
    const int g    = lane >> 2;

    const float* Qg = Q + (((size_t)b * NH + h) * SEQ + qb * 64) * HD;
    const float* Kg = K + ((size_t)b * NKV + h / NREP) * SEQ * HD;
    const float* Vg = V + ((size_t)b * NKV + h / NREP) * HD * SEQ;  // [d][s]

    const uint32_t sKs = (uint32_t)__cvta_generic_to_shared(Ks);
    const uint32_t sVs = (uint32_t)__cvta_generic_to_shared(Vs);

    auto issue_k = [&](int kt) {
        const uint32_t stb = (uint32_t)(kt & 1) * KB_BYTES;
#pragma unroll
        for (int i = 0; i < 8; i++) {
            const int f = tid + 128 * i;
            const int r = f >> 4, c4 = (f & 15) << 2;
            const uint32_t d = sKs + stb + (uint32_t)((r * QSTR + c4) * 4);
            const float* s = Kg + (size_t)kt * 64 * HD + f * 4;
            asm volatile("cp.async.cg.shared.global [%0], [%1], 16;" :: "r"(d), "l"(s));
        }
        asm volatile("cp.async.commit_group;");
    };
    auto issue_v = [&](int kt) {
#pragma unroll
        for (int i = 0; i < 8; i++) {
            const int f = tid + 128 * i;
            const int r = f >> 4, c4 = (f & 15) << 2;
            const uint32_t d = sVs + (uint32_t)((r * QSTR + c4) * 4);
            const float* s = Vg + (size_t)r * SEQ + kt * 64 + c4;
            asm volatile("cp.async.cg.shared.global [%0], [%1], 16;" :: "r"(d), "l"(s));
        }
        asm volatile("cp.async.commit_group;");
    };

    issue_k(0);
    issue_v(0);

#pragma unroll
    for (int i = 0; i < 8; i++) {
        const int f = tid + 128 * i;
        const int r = f >> 4, c4 = (f & 15) << 2;
        *(float4*)&Qs[r * QSTR + c4] = *(const float4*)&Qg[r * HD + c4];
    }
    __syncthreads();

    const int rA = warp * 16 + g;

    unsigned qf[8][4];
#pragma unroll
    for (int ks = 0; ks < 8; ks++) {
        const int k0 = ks * 8;
        qf[ks][0] = F2U(Qs[rA * QSTR + k0 + q]);
        qf[ks][1] = F2U(Qs[(rA + 8) * QSTR + k0 + q]);
        qf[ks][2] = F2U(Qs[rA * QSTR + k0 + 4 + q]);
        qf[ks][3] = F2U(Qs[(rA + 8) * QSTR + k0 + 4 + q]);
    }

    // ldmatrix bases for K / Vt B-fragments
    const int krow = (lane & 7) + ((lane >> 4) & 1) * 8;
    const int kcol = ((lane >> 3) & 1) * 4;
    const uint32_t kf4 = sKs + (uint32_t)((krow * QSTR + kcol) * 4);
    const uint32_t vf4 = sVs + (uint32_t)((krow * QSTR + kcol) * 4);

    // shfl source lanes for P C->A conversion
    const int ps0 = (lane & ~3) | (q >> 1);
    const int ps2 = ps0 + 2;
    const bool podd = (q & 1);

    float m_i[2], l_i[2], o_acc[8][4];
#pragma unroll
    for (int rh = 0; rh < 2; rh++) { m_i[rh] = -INFINITY; l_i[rh] = 0.0f; }
#pragma unroll
    for (int nt = 0; nt < 8; nt++)
#pragma unroll
        for (int j = 0; j < 4; j++) o_acc[nt][j] = 0.0f;

    for (int kt = 0; kt <= qb; kt++) {
        // K(kt) ready (V(kt) still in flight)
        asm volatile("cp.async.wait_group 1;");
        if (kt < qb) issue_k(kt + 1);      // other K stage is free (S(kt-1) closed)
        __syncthreads();

        const uint32_t kS = kf4 + (uint32_t)(kt & 1) * KB_BYTES;

        float s_acc[8][4];
#pragma unroll
        for (int nt = 0; nt < 8; nt++)
#pragma unroll
            for (int j = 0; j < 4; j++) s_acc[nt][j] = 0.0f;

#pragma unroll
        for (int ks = 0; ks < 8; ks++) {
#pragma unroll
            for (int ntp = 0; ntp < 4; ntp++) {
                unsigned b0, b1, b2, b3;
                ldsm4(b0, b1, b2, b3, kS + (uint32_t)((ntp * 16 * QSTR + ks * 8) * 4));
                mma8(s_acc[2 * ntp],     qf[ks][0], qf[ks][1], qf[ks][2], qf[ks][3], b0, b1);
                mma8(s_acc[2 * ntp + 1], qf[ks][0], qf[ks][1], qf[ks][2], qf[ks][3], b2, b3);
            }
        }

        const bool diag = (kt == qb);

#pragma unroll
        for (int rh = 0; rh < 2; rh++) {
            const int rg = qb * 64 + rA + rh * 8;
            float mx = -INFINITY;
#pragma unroll
            for (int nt = 0; nt < 8; nt++) {
#pragma unroll
                for (int j = 0; j < 2; j++) {
                    float sv = s_acc[nt][rh * 2 + j];
                    if (diag) {
                        int cg = kt * 64 + nt * 8 + (q << 1) + j;
                        if (cg > rg) sv = -INFINITY;
                    }
                    s_acc[nt][rh * 2 + j] = sv;
                    mx = fmaxf(mx, sv);
                }
            }
            mx = fmaxf(mx, __shfl_xor_sync(0xffffffffu, mx, 1));
            mx = fmaxf(mx, __shfl_xor_sync(0xffffffffu, mx, 2));

            const float mnew = fmaxf(m_i[rh], mx);
            const float sc = __expf(m_i[rh] - mnew);
            m_i[rh] = mnew;

            float rs = 0.0f;
#pragma unroll
            for (int nt = 0; nt < 8; nt++) {
#pragma unroll
                for (int j = 0; j < 2; j++) {
                    float p = __expf(s_acc[nt][rh * 2 + j] - mnew);
                    s_acc[nt][rh * 2 + j] = p;
                    rs += p;
                }
            }
            rs += __shfl_xor_sync(0xffffffffu, rs, 1);
            rs += __shfl_xor_sync(0xffffffffu, rs, 2);

            l_i[rh] = l_i[rh] * sc + rs;
#pragma unroll
            for (int nt = 0; nt < 8; nt++) {
                o_acc[nt][rh * 2]     *= sc;
                o_acc[nt][rh * 2 + 1] *= sc;
            }
        }

        // V(kt) ready (leaves K(kt+1) in flight, except at tail)
        if (kt < qb) asm volatile("cp.async.wait_group 1;");
        else         asm volatile("cp.async.wait_group 0;");
        __syncthreads();

        // O += P @ V: P A-fragments built from s_acc via shuffles.
#pragma unroll
        for (int ks = 0; ks < 8; ks++) {
            const float t00 = __shfl_sync(0xffffffffu, s_acc[ks][0], ps0);
            const float t01 = __shfl_sync(0xffffffffu, s_acc[ks][1], ps0);
            const float t10 = __shfl_sync(0xffffffffu, s_acc[ks][2], ps0);
            const float t11 = __shfl_sync(0xffffffffu, s_acc[ks][3], ps0);
            const float u00 = __shfl_sync(0xffffffffu, s_acc[ks][0], ps2);
            const float u01 = __shfl_sync(0xffffffffu, s_acc[ks][1], ps2);
            const float u10 = __shfl_sync(0xffffffffu, s_acc[ks][2], ps2);
            const float u11 = __shfl_sync(0xffffffffu, s_acc[ks][3], ps2);
            const unsigned a0 = F2U(tf32r(podd ? t01 : t00));
            const unsigned a1 = F2U(tf32r(podd ? t11 : t10));
            const unsigned a2 = F2U(tf32r(podd ? u01 : u00));
            const unsigned a3 = F2U(tf32r(podd ? u11 : u10));
#pragma unroll
            for (int ntp = 0; ntp < 4; ntp++) {
                unsigned b0, b1, b2, b3;
                ldsm4(b0, b1, b2, b3, vf4 + (uint32_t)((ntp * 16 * QSTR + ks * 8) * 4));
                mma8(o_acc[2 * ntp],     a0, a1, a2, a3, b0, b1);
                mma8(o_acc[2 * ntp + 1], a0, a1, a2, a3, b2, b3);
            }
        }
        __syncthreads();
        if (kt < qb) issue_v(kt + 1);
    }

    const float inv0 = 1.0f / l_i[0];
    const float inv1 = 1.0f / l_i[1];
#pragma unroll
    for (int nt = 0; nt < 8; nt++) {
        const int c = nt * 8 + (q << 1);
        const int r0 = qb * 64 + rA;
        float* p0 = O + ((size_t)b * SEQ + r0) * (NH * HD) + h * HD + c;
        p0[0] = tf32r(o_acc[nt][0] * inv0);
        p0[1] = tf32r(o_acc[nt][1] * inv0);
        float* p1 = O + ((size_t)b * SEQ + r0 + 8) * (NH * HD) + h * HD + c;
        p1[0] = tf32r(o_acc[nt][2] * inv1);
        p1[1] = tf32r(o_acc[nt][3] * inv1);
    }
}

// ---------------------------------------------------------------------------
// kernel_launch
// ---------------------------------------------------------------------------
extern "C" void kernel_launch(void* const* d_in, const int* in_sizes, int n_in,
                              void* d_out, int out_size)
{
    const float* hidden = (const float*)d_in[0];
    const float* wq = (const float*)d_in[1];
    const float* wk = (const float*)d_in[2];
    const float* wv = (const float*)d_in[3];
    const float* wo = (const float*)d_in[4];
    float* out = (float*)d_out;

    float *pq, *pk, *pv, *pattn, *pht;
    cudaGetSymbolAddress((void**)&pq, g_q);
    cudaGetSymbolAddress((void**)&pk, g_k);
    cudaGetSymbolAddress((void**)&pv, g_v);
    cudaGetSymbolAddress((void**)&pattn, g_attn);
    cudaGetSymbolAddress((void**)&pht, g_ht);

    const int M = BSZ * SEQ;   // 4096

    cudaFuncSetAttribute(qkv_gemm, cudaFuncAttributeMaxDynamicSharedMemorySize, GEMM_SMEM);
    cudaFuncSetAttribute(gemm_o, cudaFuncAttributeMaxDynamicSharedMemorySize, GEMM_SMEM);
    cudaFuncSetAttribute(flash_tf32, cudaFuncAttributeMaxDynamicSharedMemorySize, FLASH_SMEM);

    // 1) prologue: rope table, round hidden, transpose+round weights
    rope_fill<<<SEQ * 32 / 256, 256>>>();
    round_tf32<<<1184, 256>>>(hidden, pht, BSZ * SEQ * HIDDEN / 4);
    transpose_all<<<dim3(HIDDEN / 32, HIDDEN / 32, 4), dim3(32, 8)>>>(wq, wk, wv, wo);

    // 2) fused QKV projection + RoPE (24 N-tiles: 16 Q, 4 K, 4 V-transposed)
    qkv_gemm<<<dim3(24, M / 128), dim3(256), GEMM_SMEM>>>();

    // 3) flash attention (double-buffered K, register-resident P)
    flash_tf32<<<dim3(SEQ / 64, NH, BSZ), dim3(128), FLASH_SMEM>>>(pq, pk, pv, pattn);

    // 4) output projection
    gemm_o<<<dim3(HIDDEN / 128, M / 128), dim3(256), GEMM_SMEM>>>(out);
}

// round 14
// speedup vs baseline: 1.0138x; 1.0138x over previous
#include <cuda_runtime.h>
#include <math.h>
#include <stdint.h>

#define BSZ 2
#define SEQ 2048
#define HIDDEN 2048
#define NH 32
#define NKV 8
#define HD 64
#define NREP 4

// Scratch (static device arrays — no allocation).
__device__ float g_q[BSZ * NH * SEQ * HD];      // [b, h, s, d] tf32-rounded, pre-scaled 1/8
__device__ float g_k[BSZ * NKV * SEQ * HD];     // [b, kvh, s, d] tf32-rounded
__device__ float g_v[BSZ * NKV * HD * SEQ];     // [b, kvh, d, s] (TRANSPOSED) tf32-rounded
__device__ float g_attn[BSZ * SEQ * NH * HD];   // [b, s, h*d] tf32-rounded

__device__ float g_ht[BSZ * SEQ * HIDDEN];      // tf32-rounded hidden
__device__ float g_wqt[NH * HD * HIDDEN];       // [N,K] k-major, tf32-rounded
__device__ float g_wkt[NKV * HD * HIDDEN];
__device__ float g_wvt[NKV * HD * HIDDEN];
__device__ float g_wot[HIDDEN * NH * HD];       // [N=2048, K=2048]
__device__ float g_rope[SEQ * 64];              // [s][0:32 cos | 32:64 sin]

// ---------------------------------------------------------------------------
// Helpers
// ---------------------------------------------------------------------------
__device__ __forceinline__ float tf32r(float x) {
    unsigned u;
    asm("cvt.rna.tf32.f32 %0, %1;" : "=r"(u) : "f"(x));
    return __uint_as_float(u);
}
#define F2U __float_as_uint

__device__ __forceinline__ void mma8(float c[4],
                                     unsigned a0, unsigned a1, unsigned a2, unsigned a3,
                                     unsigned b0, unsigned b1) {
    asm volatile(
        "mma.sync.aligned.m16n8k8.row.col.f32.tf32.tf32.f32 "
        "{%0,%1,%2,%3}, {%4,%5,%6,%7}, {%8,%9}, {%0,%1,%2,%3};\n"
        : "+f"(c[0]), "+f"(c[1]), "+f"(c[2]), "+f"(c[3])
        : "r"(a0), "r"(a1), "r"(a2), "r"(a3), "r"(b0), "r"(b1));
}
__device__ __forceinline__ void ldsm4(unsigned& r0, unsigned& r1,
                                      unsigned& r2, unsigned& r3, uint32_t addr) {
    asm volatile("ldmatrix.sync.aligned.m8n8.x4.shared.b16 {%0,%1,%2,%3}, [%4];"
                 : "=r"(r0), "=r"(r1), "=r"(r2), "=r"(r3) : "r"(addr));
}

// ---------------------------------------------------------------------------
// Prologue: round hidden; merged transpose; RoPE cos/sin table
// ---------------------------------------------------------------------------
__global__ void round_tf32(const float* __restrict__ src, float* __restrict__ dst, int n4)
{
    for (int i = blockIdx.x * blockDim.x + threadIdx.x; i < n4; i += gridDim.x * blockDim.x) {
        float4 v = ((const float4*)src)[i];
        v.x = tf32r(v.x); v.y = tf32r(v.y); v.z = tf32r(v.z); v.w = tf32r(v.w);
        ((float4*)dst)[i] = v;
    }
}

__global__ void rope_fill()
{
    int idx = blockIdx.x * blockDim.x + threadIdx.x;   // 65536 total
    int s = idx >> 5, p = idx & 31;
    float inv = powf(10000.0f, -((float)(2 * p) / 64.0f));
    float ang = (float)s * inv;
    float c, si;
    sincosf(ang, &si, &c);
    g_rope[s * 64 + p] = c;
    g_rope[s * 64 + 32 + p] = si;
}

// Merged transpose: blockIdx.z selects (src,dst,Kd,Nd) segment.
// dst[n*Kd + k] = tf32r(src[k*Nd + n])
__global__ void transpose_all(const float* __restrict__ wq, const float* __restrict__ wk,
                              const float* __restrict__ wv, const float* __restrict__ wo)
{
    __shared__ float t[32][33];
    const float* src;
    float* dst;
    int Kd, Nd;
    int seg = blockIdx.z;
    if (seg == 0)      { src = wq; dst = g_wqt; Kd = HIDDEN;  Nd = NH * HD; }
    else if (seg == 1) { src = wk; dst = g_wkt; Kd = HIDDEN;  Nd = NKV * HD; }
    else if (seg == 2) { src = wv; dst = g_wvt; Kd = HIDDEN;  Nd = NKV * HD; }
    else               { src = wo; dst = g_wot; Kd = NH * HD; Nd = HIDDEN; }

    const int n0 = blockIdx.x * 32, k0 = blockIdx.y * 32;
    if (n0 >= Nd || k0 >= Kd) return;
    const int tx = threadIdx.x, ty = threadIdx.y;
#pragma unroll
    for (int i = 0; i < 4; i++)
        t[ty + i * 8][tx] = src[(size_t)(k0 + ty + i * 8) * Nd + n0 + tx];
    __syncthreads();
#pragma unroll
    for (int i = 0; i < 4; i++)
        dst[(size_t)(n0 + ty + i * 8) * Kd + k0 + tx] = tf32r(t[tx][ty + i * 8]);
}

// ---------------------------------------------------------------------------
// GEMM mainloop v3 (R12 schedule: prefetch at END of chunk — hoisting
// regressed in R13): 128x128 tile, BK=32, 3-stage cp.async, XOR-swizzled smem.
// ---------------------------------------------------------------------------
#define STAGE_B 16384u
#define GEMM_SMEM (6 * 16384)

template<int WARPS_M>
__device__ __forceinline__ void gemm_mainloop3(
    const float* __restrict__ Ag, const float* __restrict__ Bg,
    int K, float (*acc)[4])
{
    extern __shared__ float smem[];
    constexpr int MT = 8 / WARPS_M;
    constexpr int NT = 2 * WARPS_M;
    constexpr int NPAIR = NT / 2;

    const int tid  = threadIdx.x;
    const int lane = tid & 31;
    const int warp = tid >> 5;
    const int wm   = warp % WARPS_M;
    const int wn   = warp / WARPS_M;

    const uint32_t sA = (uint32_t)__cvta_generic_to_shared(smem);
    const uint32_t sB = sA + 3 * STAGE_B;

    const int lrow = tid >> 3;
    const int lj   = tid & 7;
    const uint32_t wsw = (uint32_t)((lj ^ (lrow & 7)) << 4);

    const int frow = ((lane >> 3) & 1) * 8 + (lane & 7);
    const int fjb  = lane >> 4;
    const int axr  = frow & 7;
    const uint32_t arowb = (uint32_t)((wm * MT * 16 + frow) * 128);
    const int brow = (lane & 7) + ((lane >> 4) & 1) * 8;
    const int bjb  = (lane >> 3) & 1;
    const int bxr  = brow & 7;
    const uint32_t browb = (uint32_t)((wn * NT * 8 + brow) * 128);

#define ISSUE(kc, st) do {                                                           \
    _Pragma("unroll")                                                                \
    for (int i = 0; i < 4; i++) {                                                    \
        const int r = lrow + 32 * i;                                                 \
        const float* sa = Ag + (size_t)r * K + (kc) * 32 + lj * 4;                   \
        const uint32_t da = sA + (uint32_t)(st) * STAGE_B + (uint32_t)(r * 128) + wsw; \
        asm volatile("cp.async.cg.shared.global [%0], [%1], 16;" :: "r"(da), "l"(sa)); \
    }                                                                                \
    _Pragma("unroll")                                                                \
    for (int i = 0; i < 4; i++) {                                                    \
        const int r = lrow + 32 * i;                                                 \
        const float* sb = Bg + (size_t)r * K + (kc) * 32 + lj * 4;                   \
        const uint32_t db = sB + (uint32_t)(st) * STAGE_B + (uint32_t)(r * 128) + wsw; \
        asm volatile("cp.async.cg.shared.global [%0], [%1], 16;" :: "r"(db), "l"(sb)); \
    }                                                                                \
    asm volatile("cp.async.commit_group;");                                          \
} while (0)

    const int nkc = K >> 5;
    ISSUE(0, 0);
    ISSUE(1, 1);

    for (int kc = 0; kc < nkc; kc++) {
        if (kc < nkc - 1) asm volatile("cp.async.wait_group 1;");
        else              asm volatile("cp.async.wait_group 0;");
        __syncthreads();

        const int st = kc % 3;
        const uint32_t aS = sA + (uint32_t)st * STAGE_B;
        const uint32_t bS = sB + (uint32_t)st * STAGE_B;

#pragma unroll
        for (int ks = 0; ks < 4; ks++) {
            unsigned a[MT][4];
#pragma unroll
            for (int mt = 0; mt < MT; mt++)
                ldsm4(a[mt][0], a[mt][1], a[mt][2], a[mt][3],
                      aS + arowb + (uint32_t)(mt * 2048)
                         + (uint32_t)((((2 * ks + fjb) ^ axr)) << 4));
#pragma unroll
            for (int ntp = 0; ntp < NPAIR; ntp++) {
                unsigned b0, b1, b2, b3;
                ldsm4(b0, b1, b2, b3,
                      bS + browb + (uint32_t)(ntp * 2048)
                         + (uint32_t)((((2 * ks + bjb) ^ bxr)) << 4));
#pragma unroll
                for (int mt = 0; mt < MT; mt++) {
                    mma8(acc[mt * NT + 2 * ntp],     a[mt][0], a[mt][1], a[mt][2], a[mt][3], b0, b1);
                    mma8(acc[mt * NT + 2 * ntp + 1], a[mt][0], a[mt][1], a[mt][2], a[mt][3], b2, b3);
                }
            }
        }
        if (kc + 2 < nkc) ISSUE(kc + 2, (kc + 2) % 3);
    }
#undef ISSUE
}

// ---------------------------------------------------------------------------
// Fused QKV projection + RoPE epilogue (cos/sin from g_rope table).
// V is stored TRANSPOSED [b,kvh,d,s].
// ---------------------------------------------------------------------------
__global__ __launch_bounds__(256, 2)
void qkv_gemm()
{
    const int bx = blockIdx.x, by = blockIdx.y;
    const int tid = threadIdx.x;
    const int lane = tid & 31, warp = tid >> 5;
    const int wm = warp % 4, wn = warp / 4;
    const int q = lane & 3, g = lane >> 2;

    const float* W;
    float* Out;
    int cb, heads;
    bool rope;
    float oscale;
    if (bx < 16)      { W = g_wqt; Out = g_q; cb = bx * 128;        heads = NH;  rope = true;  oscale = 0.125f; }
    else if (bx < 20) { W = g_wkt; Out = g_k; cb = (bx - 16) * 128; heads = NKV; rope = true;  oscale = 1.0f; }
    else              { W = g_wvt; Out = g_v; cb = (bx - 20) * 128; heads = NKV; rope = false; oscale = 1.0f; }

    float acc[16][4];
#pragma unroll
    for (int i = 0; i < 16; i++)
#pragma unroll
        for (int j = 0; j < 4; j++) acc[i][j] = 0.0f;

    gemm_mainloop3<4>(g_ht + (size_t)(by * 128) * HIDDEN,
                      W + (size_t)cb * HIDDEN, HIDDEN, acc);

    if (rope) {
#pragma unroll
        for (int mt = 0; mt < 2; mt++) {
#pragma unroll
            for (int rh = 0; rh < 2; rh++) {
                const int m = by * 128 + wm * 32 + mt * 16 + g + rh * 8;
                const int ss = m & (SEQ - 1);
                const float* rp = g_rope + ss * 64;
#pragma unroll
                for (int ntp = 0; ntp < 4; ntp++) {
                    const int f = ntp * 8 + (q << 1);
                    const float2 cc = *(const float2*)(rp + f);
                    const float2 sn = *(const float2*)(rp + 32 + f);
                    {
                        const float x1 = acc[mt * 8 + ntp][rh * 2];
                        const float x2 = acc[mt * 8 + ntp + 4][rh * 2];
                        acc[mt * 8 + ntp][rh * 2]     = x1 * cc.x - x2 * sn.x;
                        acc[mt * 8 + ntp + 4][rh * 2] = x2 * cc.x + x1 * sn.x;
                    }
                    {
                        const float x1 = acc[mt * 8 + ntp][rh * 2 + 1];
                        const float x2 = acc[mt * 8 + ntp + 4][rh * 2 + 1];
                        acc[mt * 8 + ntp][rh * 2 + 1]     = x1 * cc.y - x2 * sn.y;
                        acc[mt * 8 + ntp + 4][rh * 2 + 1] = x2 * cc.y + x1 * sn.y;
                    }
                }
            }
        }
    }

#pragma unroll
    for (int mt = 0; mt < 2; mt++) {
        const int row = by * 128 + wm * 32 + mt * 16 + g;
#pragma unroll
        for (int nt = 0; nt < 8; nt++) {
            const int col = cb + wn * 64 + nt * 8 + (q << 1);
            const int hh = col / HD, dd = col & (HD - 1);
#pragma unroll
            for (int rh = 0; rh < 2; rh++) {
                const int m = row + rh * 8;
                const int bb = m >> 11, ss = m & (SEQ - 1);
                if (rope) {
                    float* p = Out + (((size_t)bb * heads + hh) * SEQ + ss) * HD + dd;
                    p[0] = tf32r(acc[mt * 8 + nt][rh * 2]     * oscale);
                    p[1] = tf32r(acc[mt * 8 + nt][rh * 2 + 1] * oscale);
                } else {
                    float* p = Out + (((size_t)bb * heads + hh) * HD + dd) * SEQ + ss;
                    p[0]   = tf32r(acc[mt * 8 + nt][rh * 2]);
                    p[SEQ] = tf32r(acc[mt * 8 + nt][rh * 2 + 1]);
                }
            }
        }
    }
}

// ---------------------------------------------------------------------------
// Output projection
// ---------------------------------------------------------------------------
__global__ __launch_bounds__(256, 2)
void gemm_o(float* __restrict__ C)
{
    const int bx = blockIdx.x, by = blockIdx.y;
    const int tid = threadIdx.x;
    const int lane = tid & 31, warp = tid >> 5;
    const int wm = warp % 2, wn = warp / 2;
    const int q = lane & 3, g = lane >> 2;

    float acc[16][4];
#pragma unroll
    for (int i = 0; i < 16; i++)
#pragma unroll
        for (int j = 0; j < 4; j++) acc[i][j] = 0.0f;

    gemm_mainloop3<2>(g_attn + (size_t)(by * 128) * HIDDEN,
                      g_wot + (size_t)(bx * 128) * HIDDEN, HIDDEN, acc);

#pragma unroll
    for (int mt = 0; mt < 4; mt++) {
        const int row = by * 128 + wm * 64 + mt * 16 + g;
#pragma unroll
        for (int nt = 0; nt < 4; nt++) {
            const int col = bx * 128 + wn * 32 + nt * 8 + (q << 1);
            *(float2*)(C + (size_t)row * HIDDEN + col) =
                make_float2(acc[mt * 4 + nt][0], acc[mt * 4 + nt][1]);
            *(float2*)(C + (size_t)(row + 8) * HIDDEN + col) =
                make_float2(acc[mt * 4 + nt][2], acc[mt * 4 + nt][3]);
        }
    }
}

// ---------------------------------------------------------------------------
// Flash attention v3: 128-row Q tiles, 4 warps x 32 q-rows each (2 m-tiles),
// 128 threads, occ 2 (256-reg budget). Every K/V ldsm4 feeds 4 MMAs (2x the
// old reuse) -> halves LDSM bytes per FLOP (the measured L1 bottleneck).
// R12 pipeline schedule (single-buffer K/V alternating), shuffle-resident P.
// ---------------------------------------------------------------------------
#define QSTR 68
#define FLASH_SMEM ((128 + 64 + 64) * QSTR * 4)   // Qs(staging) + Ks + Vs = 69632

__global__ __launch_bounds__(128, 2)
void flash_tf32(const float* __restrict__ Q, const float* __restrict__ K,
                const float* __restrict__ V, float* __restrict__ O)
{
    extern __shared__ float sm[];
    float* Qs = sm;                        // [128][QSTR] staging (dead after hoist)
    float* Ks = Qs + 128 * QSTR;           // [64 keys][QSTR]
    float* Vs = Ks + 64 * QSTR;            // [64 d][QSTR] (transposed V tile)

    const int qb   = gridDim.x - 1 - blockIdx.x;   // heavy blocks first
    const int h    = blockIdx.y;
    const int b    = blockIdx.z;
    const int tid  = threadIdx.x;
    const int lane = tid & 31;
    const int warp = tid >> 5;
    const int q    = lane & 3;
    const int g    = lane >> 2;

    const float* Qg = Q + (((size_t)b * NH + h) * SEQ + qb * 128) * HD;
    const float* Kg = K + ((size_t)b * NKV + h / NREP) * SEQ * HD;
    const float* Vg = V + ((size_t)b * NKV + h / NREP) * HD * SEQ;  // [d][s]

    const uint32_t sKs = (uint32_t)__cvta_generic_to_shared(Ks);
    const uint32_t sVs = (uint32_t)__cvta_generic_to_shared(Vs);

    auto issue_k = [&](int kt) {
#pragma unroll
        for (int i = 0; i < 8; i++) {
            const int f = tid + 128 * i;
            const int r = f >> 4, c4 = (f & 15) << 2;
            const uint32_t d = sKs + (uint32_t)((r * QSTR + c4) * 4);
            const float* s = Kg + (size_t)kt * 64 * HD + f * 4;
            asm volatile("cp.async.cg.shared.global [%0], [%1], 16;" :: "r"(d), "l"(s));
        }
        asm volatile("cp.async.commit_group;");
    };
    auto issue_v = [&](int kt) {
#pragma unroll
        for (int i = 0; i < 8; i++) {
            const int f = tid + 128 * i;
            const int r = f >> 4, c4 = (f & 15) << 2;
            const uint32_t d = sVs + (uint32_t)((r * QSTR + c4) * 4);
            const float* s = Vg + (size_t)r * SEQ + kt * 64 + c4;
            asm volatile("cp.async.cg.shared.global [%0], [%1], 16;" :: "r"(d), "l"(s));
        }
        asm volatile("cp.async.commit_group;");
    };

    issue_k(0);
    issue_v(0);

    // Stage Q: 128 rows x 64 = 2048 float4, 16 per thread
#pragma unroll
    for (int i = 0; i < 16; i++) {
        const int f = tid + 128 * i;
        const int r = f >> 4, c4 = (f & 15) << 2;
        *(float4*)&Qs[r * QSTR + c4] = *(const float4*)&Qg[r * HD + c4];
    }
    __syncthreads();

    // Hoist Q fragments: 2 m-tiles x 8 k-slabs x 4 regs
    unsigned qf[2][8][4];
#pragma unroll
    for (int mt = 0; mt < 2; mt++) {
        const int r0 = warp * 32 + mt * 16 + g;
#pragma unroll
        for (int ks = 0; ks < 8; ks++) {
            const int k0 = ks * 8;
            qf[mt][ks][0] = F2U(Qs[r0 * QSTR + k0 + q]);
            qf[mt][ks][1] = F2U(Qs[(r0 + 8) * QSTR + k0 + q]);
            qf[mt][ks][2] = F2U(Qs[r0 * QSTR + k0 + 4 + q]);
            qf[mt][ks][3] = F2U(Qs[(r0 + 8) * QSTR + k0 + 4 + q]);
        }
    }

    // ldmatrix bases for K / Vt B-fragments
    const int krow = (lane & 7) + ((lane >> 4) & 1) * 8;
    const int kcol = ((lane >> 3) & 1) * 4;
    const uint32_t kf4 = sKs + (uint32_t)((krow * QSTR + kcol) * 4);
    const uint32_t vf4 = sVs + (uint32_t)((krow * QSTR + kcol) * 4);

    // shfl source lanes for P C->A conversion
    const int ps0 = (lane & ~3) | (q >> 1);
    const int ps2 = ps0 + 2;
    const bool podd = (q & 1);

    float m_i[2][2], l_i[2][2], o_acc[2][8][4];
#pragma unroll
    for (int mt = 0; mt < 2; mt++)
#pragma unroll
        for (int rh = 0; rh < 2; rh++) { m_i[mt][rh] = -INFINITY; l_i[mt][rh] = 0.0f; }
#pragma unroll
    for (int mt = 0; mt < 2; mt++)
#pragma unroll
        for (int nt = 0; nt < 8; nt++)
#pragma unroll
            for (int j = 0; j < 4; j++) o_acc[mt][nt][j] = 0.0f;

    const int nkt = 2 * qb + 2;

    for (int kt = 0; kt < nkt; kt++) {
        asm volatile("cp.async.wait_group 1;");
        __syncthreads();

        // S = Q @ K^T : 2 m-tiles share every K fragment (4 mma per ldsm4)
        float s_acc[2][8][4];
#pragma unroll
        for (int mt = 0; mt < 2; mt++)
#pragma unroll
            for (int nt = 0; nt < 8; nt++)
#pragma unroll
                for (int j = 0; j < 4; j++) s_acc[mt][nt][j] = 0.0f;

#pragma unroll
        for (int ks = 0; ks < 8; ks++) {
#pragma unroll
            for (int ntp = 0; ntp < 4; ntp++) {
                unsigned b0, b1, b2, b3;
                ldsm4(b0, b1, b2, b3, kf4 + (uint32_t)((ntp * 16 * QSTR + ks * 8) * 4));
#pragma unroll
                for (int mt = 0; mt < 2; mt++) {
                    mma8(s_acc[mt][2 * ntp],     qf[mt][ks][0], qf[mt][ks][1], qf[mt][ks][2], qf[mt][ks][3], b0, b1);
                    mma8(s_acc[mt][2 * ntp + 1], qf[mt][ks][0], qf[mt][ks][1], qf[mt][ks][2], qf[mt][ks][3], b2, b3);
                }
            }
        }

        const bool diag = (kt >= 2 * qb);

        // Online softmax per (mt, row-half)
#pragma unroll
        for (int mt = 0; mt < 2; mt++) {
#pragma unroll
            for (int rh = 0; rh < 2; rh++) {
                const int rg = qb * 128 + warp * 32 + mt * 16 + g + rh * 8;
                float mx = -INFINITY;
#pragma unroll
                for (int nt = 0; nt < 8; nt++) {
#pragma unroll
                    for (int j = 0; j < 2; j++) {
                        float sv = s_acc[mt][nt][rh * 2 + j];
                        if (diag) {
                            int cg = kt * 64 + nt * 8 + (q << 1) + j;
                            if (cg > rg) sv = -INFINITY;
                        }
                        s_acc[mt][nt][rh * 2 + j] = sv;
                        mx = fmaxf(mx, sv);
                    }
                }
                mx = fmaxf(mx, __shfl_xor_sync(0xffffffffu, mx, 1));
                mx = fmaxf(mx, __shfl_xor_sync(0xffffffffu, mx, 2));

                const float mnew = fmaxf(m_i[mt][rh], mx);
                const float sc = __expf(m_i[mt][rh] - mnew);
                m_i[mt][rh] = mnew;

                float rs = 0.0f;
#pragma unroll
                for (int nt = 0; nt < 8; nt++) {
#pragma unroll
                    for (int j = 0; j < 2; j++) {
                        float p = __expf(s_acc[mt][nt][rh * 2 + j] - mnew);
                        s_acc[mt][nt][rh * 2 + j] = p;
                        rs += p;
                    }
                }
                rs += __shfl_xor_sync(0xffffffffu, rs, 1);
                rs += __shfl_xor_sync(0xffffffffu, rs, 2);

                l_i[mt][rh] = l_i[mt][rh] * sc + rs;
#pragma unroll
                for (int nt = 0; nt < 8; nt++) {
                    o_acc[mt][nt][rh * 2]     *= sc;
                    o_acc[mt][nt][rh * 2 + 1] *= sc;
                }
            }
        }

        asm volatile("cp.async.wait_group 0;");
        __syncthreads();
        if (kt + 1 < nkt) issue_k(kt + 1);

        // O += P @ V : P A-fragments from s_acc via shuffles; each V ldsm4
        // feeds 4 mma (2 m-tiles x 2 n-tiles).
#pragma unroll
        for (int ks = 0; ks < 8; ks++) {
            unsigned a[2][4];
#pragma unroll
            for (int mt = 0; mt < 2; mt++) {
                const float t00 = __shfl_sync(0xffffffffu, s_acc[mt][ks][0], ps0);
                const float t01 = __shfl_sync(0xffffffffu, s_acc[mt][ks][1], ps0);
                const float t10 = __shfl_sync(0xffffffffu, s_acc[mt][ks][2], ps0);
                const float t11 = __shfl_sync(0xffffffffu, s_acc[mt][ks][3], ps0);
                const float u00 = __shfl_sync(0xffffffffu, s_acc[mt][ks][0], ps2);
                const float u01 = __shfl_sync(0xffffffffu, s_acc[mt][ks][1], ps2);
                const float u10 = __shfl_sync(0xffffffffu, s_acc[mt][ks][2], ps2);
                const float u11 = __shfl_sync(0xffffffffu, s_acc[mt][ks][3], ps2);
                a[mt][0] = F2U(tf32r(podd ? t01 : t00));
                a[mt][1] = F2U(tf32r(podd ? t11 : t10));
                a[mt][2] = F2U(tf32r(podd ? u01 : u00));
                a[mt][3] = F2U(tf32r(podd ? u11 : u10));
            }
#pragma unroll
            for (int ntp = 0; ntp < 4; ntp++) {
                unsigned b0, b1, b2, b3;
                ldsm4(b0, b1, b2, b3, vf4 + (uint32_t)((ntp * 16 * QSTR + ks * 8) * 4));
#pragma unroll
                for (int mt = 0; mt < 2; mt++) {
                    mma8(o_acc[mt][2 * ntp],     a[mt][0], a[mt][1], a[mt][2], a[mt][3], b0, b1);
                    mma8(o_acc[mt][2 * ntp + 1], a[mt][0], a[mt][1], a[mt][2], a[mt][3], b2, b3);
                }
            }
        }
        __syncthreads();
        if (kt + 1 < nkt) issue_v(kt + 1);
    }

    // Normalize, tf32-round (feeds gemm_o), write [b, s, h*HD]
#pragma unroll
    for (int mt = 0; mt < 2; mt++) {
        const float inv0 = 1.0f / l_i[mt][0];
        const float inv1 = 1.0f / l_i[mt][1];
        const int r0 = qb * 128 + warp * 32 + mt * 16 + g;
#pragma unroll
        for (int nt = 0; nt < 8; nt++) {
            const int c = nt * 8 + (q << 1);
            float* p0 = O + ((size_t)b * SEQ + r0) * (NH * HD) + h * HD + c;
            p0[0] = tf32r(o_acc[mt][nt][0] * inv0);
            p0[1] = tf32r(o_acc[mt][nt][1] * inv0);
            float* p1 = O + ((size_t)b * SEQ + r0 + 8) * (NH * HD) + h * HD + c;
            p1[0] = tf32r(o_acc[mt][nt][2] * inv1);
            p1[1] = tf32r(o_acc[mt][nt][3] * inv1);
        }
    }
}

// ---------------------------------------------------------------------------
// kernel_launch
// ---------------------------------------------------------------------------
extern "C" void kernel_launch(void* const* d_in, const int* in_sizes, int n_in,
                              void* d_out, int out_size)
{
    const float* hidden = (const float*)d_in[0];
    const float* wq = (const float*)d_in[1];
    const float* wk = (const float*)d_in[2];
    const float* wv = (const float*)d_in[3];
    const float* wo = (const float*)d_in[4];
    float* out = (float*)d_out;

    float *pq, *pk, *pv, *pattn, *pht;
    cudaGetSymbolAddress((void**)&pq, g_q);
    cudaGetSymbolAddress((void**)&pk, g_k);
    cudaGetSymbolAddress((void**)&pv, g_v);
    cudaGetSymbolAddress((void**)&pattn, g_attn);
    cudaGetSymbolAddress((void**)&pht, g_ht);

    const int M = BSZ * SEQ;   // 4096

    cudaFuncSetAttribute(qkv_gemm, cudaFuncAttributeMaxDynamicSharedMemorySize, GEMM_SMEM);
    cudaFuncSetAttribute(gemm_o, cudaFuncAttributeMaxDynamicSharedMemorySize, GEMM_SMEM);
    cudaFuncSetAttribute(flash_tf32, cudaFuncAttributeMaxDynamicSharedMemorySize, FLASH_SMEM);

    // 1) prologue: rope table, round hidden, transpose+round weights
    rope_fill<<<SEQ * 32 / 256, 256>>>();
    round_tf32<<<1184, 256>>>(hidden, pht, BSZ * SEQ * HIDDEN / 4);
    transpose_all<<<dim3(HIDDEN / 32, HIDDEN / 32, 4), dim3(32, 8)>>>(wq, wk, wv, wo);

    // 2) fused QKV projection + RoPE (24 N-tiles: 16 Q, 4 K, 4 V-transposed)
    qkv_gemm<<<dim3(24, M / 128), dim3(256), GEMM_SMEM>>>();

    // 3) flash attention (128-row Q tiles, 32 q-rows/warp, 2x B-fragment reuse)
    flash_tf32<<<dim3(SEQ / 128, NH, BSZ), dim3(128), FLASH_SMEM>>>(pq, pk, pv, pattn);

    // 4) output projection
    gemm_o<<<dim3(HIDDEN / 128, M / 128), dim3(256), GEMM_SMEM>>>(out);
}

// round 15
// speedup vs baseline: 1.0376x; 1.0234x over previous
#include <cuda_runtime.h>
#include <math.h>
#include <stdint.h>

#define BSZ 2
#define SEQ 2048
#define HIDDEN 2048
#define NH 32
#define NKV 8
#define HD 64
#define NREP 4

// Scratch (static device arrays — no allocation).
__device__ float g_q[BSZ * NH * SEQ * HD];      // [b, h, s, d] tf32-rounded, pre-scaled 1/8
__device__ float g_k[BSZ * NKV * SEQ * HD];     // [b, kvh, s, d] tf32-rounded
__device__ float g_v[BSZ * NKV * HD * SEQ];     // [b, kvh, d, s] (TRANSPOSED) tf32-rounded
__device__ float g_attn[BSZ * SEQ * NH * HD];   // [b, s, h*d] tf32-rounded

__device__ float g_wqt[NH * HD * HIDDEN];       // [N,K] k-major, tf32-rounded
__device__ float g_wkt[NKV * HD * HIDDEN];
__device__ float g_wvt[NKV * HD * HIDDEN];
__device__ float g_wot[HIDDEN * NH * HD];       // [N=2048, K=2048]
__device__ float g_rope[SEQ * 64];              // [s][0:32 cos | 32:64 sin]

// ---------------------------------------------------------------------------
// Helpers
// ---------------------------------------------------------------------------
__device__ __forceinline__ float tf32r(float x) {
    unsigned u;
    asm("cvt.rna.tf32.f32 %0, %1;" : "=r"(u) : "f"(x));
    return __uint_as_float(u);
}
#define F2U __float_as_uint

__device__ __forceinline__ void mma8(float c[4],
                                     unsigned a0, unsigned a1, unsigned a2, unsigned a3,
                                     unsigned b0, unsigned b1) {
    asm volatile(
        "mma.sync.aligned.m16n8k8.row.col.f32.tf32.tf32.f32 "
        "{%0,%1,%2,%3}, {%4,%5,%6,%7}, {%8,%9}, {%0,%1,%2,%3};\n"
        : "+f"(c[0]), "+f"(c[1]), "+f"(c[2]), "+f"(c[3])
        : "r"(a0), "r"(a1), "r"(a2), "r"(a3), "r"(b0), "r"(b1));
}
__device__ __forceinline__ void ldsm4(unsigned& r0, unsigned& r1,
                                      unsigned& r2, unsigned& r3, uint32_t addr) {
    asm volatile("ldmatrix.sync.aligned.m8n8.x4.shared.b16 {%0,%1,%2,%3}, [%4];"
                 : "=r"(r0), "=r"(r1), "=r"(r2), "=r"(r3) : "r"(addr));
}

// ---------------------------------------------------------------------------
// Prologue (single launch): weight transposes (+tf32 round) and RoPE table.
// blockIdx.z: 0..3 = transpose segments, 4 = rope table fill.
// ---------------------------------------------------------------------------
__global__ void prologue_all(const float* __restrict__ wq, const float* __restrict__ wk,
                             const float* __restrict__ wv, const float* __restrict__ wo)
{
    __shared__ float t[32][33];
    const int seg = blockIdx.z;
    const int tx = threadIdx.x, ty = threadIdx.y;

    if (seg == 4) {
        // RoPE table: 2048 positions x 32 freqs = 65536 entries; 256 blocks.
        const int flat = blockIdx.y * gridDim.x + blockIdx.x;
        if (flat >= 256) return;
        const int idx = flat * 256 + ty * 32 + tx;
        const int s = idx >> 5, p = idx & 31;
        float inv = powf(10000.0f, -((float)(2 * p) / 64.0f));
        float ang = (float)s * inv;
        float c, si;
        sincosf(ang, &si, &c);
        g_rope[s * 64 + p] = c;
        g_rope[s * 64 + 32 + p] = si;
        return;
    }

    const float* src;
    float* dst;
    int Kd, Nd;
    if (seg == 0)      { src = wq; dst = g_wqt; Kd = HIDDEN;  Nd = NH * HD; }
    else if (seg == 1) { src = wk; dst = g_wkt; Kd = HIDDEN;  Nd = NKV * HD; }
    else if (seg == 2) { src = wv; dst = g_wvt; Kd = HIDDEN;  Nd = NKV * HD; }
    else               { src = wo; dst = g_wot; Kd = NH * HD; Nd = HIDDEN; }

    const int n0 = blockIdx.x * 32, k0 = blockIdx.y * 32;
    if (n0 >= Nd || k0 >= Kd) return;
#pragma unroll
    for (int i = 0; i < 4; i++)
        t[ty + i * 8][tx] = src[(size_t)(k0 + ty + i * 8) * Nd + n0 + tx];
    __syncthreads();
#pragma unroll
    for (int i = 0; i < 4; i++)
        dst[(size_t)(n0 + ty + i * 8) * Kd + k0 + tx] = tf32r(t[tx][ty + i * 8]);
}

// ---------------------------------------------------------------------------
// GEMM mainloop v3 (R12 schedule): 128x128 tile, BK=32, 3-stage cp.async,
// XOR-swizzled smem, both fragments via ldmatrix.
// CVT_A: apply tf32 rounding to A fragments after ldsm (A source is raw fp32).
// ---------------------------------------------------------------------------
#define STAGE_B 16384u
#define GEMM_SMEM (6 * 16384)

template<int WARPS_M, bool CVT_A>
__device__ __forceinline__ void gemm_mainloop3(
    const float* __restrict__ Ag, const float* __restrict__ Bg,
    int K, float (*acc)[4])
{
    extern __shared__ float smem[];
    constexpr int MT = 8 / WARPS_M;
    constexpr int NT = 2 * WARPS_M;
    constexpr int NPAIR = NT / 2;

    const int tid  = threadIdx.x;
    const int lane = tid & 31;
    const int warp = tid >> 5;
    const int wm   = warp % WARPS_M;
    const int wn   = warp / WARPS_M;

    const uint32_t sA = (uint32_t)__cvta_generic_to_shared(smem);
    const uint32_t sB = sA + 3 * STAGE_B;

    const int lrow = tid >> 3;
    const int lj   = tid & 7;
    const uint32_t wsw = (uint32_t)((lj ^ (lrow & 7)) << 4);

    const int frow = ((lane >> 3) & 1) * 8 + (lane & 7);
    const int fjb  = lane >> 4;
    const int axr  = frow & 7;
    const uint32_t arowb = (uint32_t)((wm * MT * 16 + frow) * 128);
    const int brow = (lane & 7) + ((lane >> 4) & 1) * 8;
    const int bjb  = (lane >> 3) & 1;
    const int bxr  = brow & 7;
    const uint32_t browb = (uint32_t)((wn * NT * 8 + brow) * 128);

#define ISSUE(kc, st) do {                                                           \
    _Pragma("unroll")                                                                \
    for (int i = 0; i < 4; i++) {                                                    \
        const int r = lrow + 32 * i;                                                 \
        const float* sa = Ag + (size_t)r * K + (kc) * 32 + lj * 4;                   \
        const uint32_t da = sA + (uint32_t)(st) * STAGE_B + (uint32_t)(r * 128) + wsw; \
        asm volatile("cp.async.cg.shared.global [%0], [%1], 16;" :: "r"(da), "l"(sa)); \
    }                                                                                \
    _Pragma("unroll")                                                                \
    for (int i = 0; i < 4; i++) {                                                    \
        const int r = lrow + 32 * i;                                                 \
        const float* sb = Bg + (size_t)r * K + (kc) * 32 + lj * 4;                   \
        const uint32_t db = sB + (uint32_t)(st) * STAGE_B + (uint32_t)(r * 128) + wsw; \
        asm volatile("cp.async.cg.shared.global [%0], [%1], 16;" :: "r"(db), "l"(sb)); \
    }                                                                                \
    asm volatile("cp.async.commit_group;");                                          \
} while (0)

    const int nkc = K >> 5;
    ISSUE(0, 0);
    ISSUE(1, 1);

    for (int kc = 0; kc < nkc; kc++) {
        if (kc < nkc - 1) asm volatile("cp.async.wait_group 1;");
        else              asm volatile("cp.async.wait_group 0;");
        __syncthreads();

        const int st = kc % 3;
        const uint32_t aS = sA + (uint32_t)st * STAGE_B;
        const uint32_t bS = sB + (uint32_t)st * STAGE_B;

#pragma unroll
        for (int ks = 0; ks < 4; ks++) {
            unsigned a[MT][4];
#pragma unroll
            for (int mt = 0; mt < MT; mt++) {
                ldsm4(a[mt][0], a[mt][1], a[mt][2], a[mt][3],
                      aS + arowb + (uint32_t)(mt * 2048)
                         + (uint32_t)((((2 * ks + fjb) ^ axr)) << 4));
                if (CVT_A) {
#pragma unroll
                    for (int j = 0; j < 4; j++)
                        a[mt][j] = F2U(tf32r(__uint_as_float(a[mt][j])));
                }
            }
#pragma unroll
            for (int ntp = 0; ntp < NPAIR; ntp++) {
                unsigned b0, b1, b2, b3;
                ldsm4(b0, b1, b2, b3,
                      bS + browb + (uint32_t)(ntp * 2048)
                         + (uint32_t)((((2 * ks + bjb) ^ bxr)) << 4));
#pragma unroll
                for (int mt = 0; mt < MT; mt++) {
                    mma8(acc[mt * NT + 2 * ntp],     a[mt][0], a[mt][1], a[mt][2], a[mt][3], b0, b1);
                    mma8(acc[mt * NT + 2 * ntp + 1], a[mt][0], a[mt][1], a[mt][2], a[mt][3], b2, b3);
                }
            }
        }
        if (kc + 2 < nkc) ISSUE(kc + 2, (kc + 2) % 3);
    }
#undef ISSUE
}

// ---------------------------------------------------------------------------
// Fused QKV projection + RoPE epilogue (cos/sin from g_rope table).
// A = raw hidden (tf32-rounded on fragments). V stored TRANSPOSED [b,kvh,d,s].
// ---------------------------------------------------------------------------
__global__ __launch_bounds__(256, 2)
void qkv_gemm(const float* __restrict__ hidden)
{
    const int bx = blockIdx.x, by = blockIdx.y;
    const int tid = threadIdx.x;
    const int lane = tid & 31, warp = tid >> 5;
    const int wm = warp % 4, wn = warp / 4;
    const int q = lane & 3, g = lane >> 2;

    const float* W;
    float* Out;
    int cb, heads;
    bool rope;
    float oscale;
    if (bx < 16)      { W = g_wqt; Out = g_q; cb = bx * 128;        heads = NH;  rope = true;  oscale = 0.125f; }
    else if (bx < 20) { W = g_wkt; Out = g_k; cb = (bx - 16) * 128; heads = NKV; rope = true;  oscale = 1.0f; }
    else              { W = g_wvt; Out = g_v; cb = (bx - 20) * 128; heads = NKV; rope = false; oscale = 1.0f; }

    float acc[16][4];
#pragma unroll
    for (int i = 0; i < 16; i++)
#pragma unroll
        for (int j = 0; j < 4; j++) acc[i][j] = 0.0f;

    gemm_mainloop3<4, true>(hidden + (size_t)(by * 128) * HIDDEN,
                            W + (size_t)cb * HIDDEN, HIDDEN, acc);

    if (rope) {
#pragma unroll
        for (int mt = 0; mt < 2; mt++) {
#pragma unroll
            for (int rh = 0; rh < 2; rh++) {
                const int m = by * 128 + wm * 32 + mt * 16 + g + rh * 8;
                const int ss = m & (SEQ - 1);
                const float* rp = g_rope + ss * 64;
#pragma unroll
                for (int ntp = 0; ntp < 4; ntp++) {
                    const int f = ntp * 8 + (q << 1);
                    const float2 cc = *(const float2*)(rp + f);
                    const float2 sn = *(const float2*)(rp + 32 + f);
                    {
                        const float x1 = acc[mt * 8 + ntp][rh * 2];
                        const float x2 = acc[mt * 8 + ntp + 4][rh * 2];
                        acc[mt * 8 + ntp][rh * 2]     = x1 * cc.x - x2 * sn.x;
                        acc[mt * 8 + ntp + 4][rh * 2] = x2 * cc.x + x1 * sn.x;
                    }
                    {
                        const float x1 = acc[mt * 8 + ntp][rh * 2 + 1];
                        const float x2 = acc[mt * 8 + ntp + 4][rh * 2 + 1];
                        acc[mt * 8 + ntp][rh * 2 + 1]     = x1 * cc.y - x2 * sn.y;
                        acc[mt * 8 + ntp + 4][rh * 2 + 1] = x2 * cc.y + x1 * sn.y;
                    }
                }
            }
        }
    }

#pragma unroll
    for (int mt = 0; mt < 2; mt++) {
        const int row = by * 128 + wm * 32 + mt * 16 + g;
#pragma unroll
        for (int nt = 0; nt < 8; nt++) {
            const int col = cb + wn * 64 + nt * 8 + (q << 1);
            const int hh = col / HD, dd = col & (HD - 1);
#pragma unroll
            for (int rh = 0; rh < 2; rh++) {
                const int m = row + rh * 8;
                const int bb = m >> 11, ss = m & (SEQ - 1);
                if (rope) {
                    float* p = Out + (((size_t)bb * heads + hh) * SEQ + ss) * HD + dd;
                    p[0] = tf32r(acc[mt * 8 + nt][rh * 2]     * oscale);
                    p[1] = tf32r(acc[mt * 8 + nt][rh * 2 + 1] * oscale);
                } else {
                    float* p = Out + (((size_t)bb * heads + hh) * HD + dd) * SEQ + ss;
                    p[0]   = tf32r(acc[mt * 8 + nt][rh * 2]);
                    p[SEQ] = tf32r(acc[mt * 8 + nt][rh * 2 + 1]);
                }
            }
        }
    }
}

// ---------------------------------------------------------------------------
// Output projection
// ---------------------------------------------------------------------------
__global__ __launch_bounds__(256, 2)
void gemm_o(float* __restrict__ C)
{
    const int bx = blockIdx.x, by = blockIdx.y;
    const int tid = threadIdx.x;
    const int lane = tid & 31, warp = tid >> 5;
    const int wm = warp % 2, wn = warp / 2;
    const int q = lane & 3, g = lane >> 2;

    float acc[16][4];
#pragma unroll
    for (int i = 0; i < 16; i++)
#pragma unroll
        for (int j = 0; j < 4; j++) acc[i][j] = 0.0f;

    gemm_mainloop3<2, false>(g_attn + (size_t)(by * 128) * HIDDEN,
                             g_wot + (size_t)(bx * 128) * HIDDEN, HIDDEN, acc);

#pragma unroll
    for (int mt = 0; mt < 4; mt++) {
        const int row = by * 128 + wm * 64 + mt * 16 + g;
#pragma unroll
        for (int nt = 0; nt < 4; nt++) {
            const int col = bx * 128 + wn * 32 + nt * 8 + (q << 1);
            *(float2*)(C + (size_t)row * HIDDEN + col) =
                make_float2(acc[mt * 4 + nt][0], acc[mt * 4 + nt][1]);
            *(float2*)(C + (size_t)(row + 8) * HIDDEN + col) =
                make_float2(acc[mt * 4 + nt][2], acc[mt * 4 + nt][3]);
        }
    }
}

// ---------------------------------------------------------------------------
// Flash attention (R12-proven shape, verbatim): 64-row Q tiles, 4 warps,
// occ 3, cp.async K/V alternating pipeline, shuffle-resident P,
// K/Vt fragments via ldsm4, heavy blocks first.
// ---------------------------------------------------------------------------
#define QSTR 68
#define FLASH_SMEM ((64 * QSTR * 3) * 4)

__global__ __launch_bounds__(128, 3)
void flash_tf32(const float* __restrict__ Q, const float* __restrict__ K,
                const float* __restrict__ V, float* __restrict__ O)
{
    extern __shared__ float sm[];
    float* Qs = sm;
    float* Ks = Qs + 64 * QSTR;
    float* Vs = Ks + 64 * QSTR;       // [64 d][QSTR] (transposed V tile)

    const int qb   = gridDim.x - 1 - blockIdx.x;   // heavy blocks first
    const int h    = blockIdx.y;
    const int b    = blockIdx.z;
    const int tid  = threadIdx.x;
    const int lane = tid & 31;
    const int warp = tid >> 5;
    const int q    = lane & 3;
    const int g    = lane >> 2;

    const float* Qg = Q + (((size_t)b * NH + h) * SEQ + qb * 64) * HD;
    const float* Kg = K + ((size_t)b * NKV + h / NREP) * SEQ * HD;
    const float* Vg = V + ((size_t)b * NKV + h / NREP) * HD * SEQ;  // [d][s]

    const uint32_t sKs = (uint32_t)__cvta_generic_to_shared(Ks);
    const uint32_t sVs = (uint32_t)__cvta_generic_to_shared(Vs);

    auto issue_k = [&](int kt) {
#pragma unroll
        for (int i = 0; i < 8; i++) {
            const int f = tid + 128 * i;
            const int r = f >> 4, c4 = (f & 15) << 2;
            const uint32_t d = sKs + (uint32_t)((r * QSTR + c4) * 4);
            const float* s = Kg + (size_t)kt * 64 * HD + f * 4;
            asm volatile("cp.async.cg.shared.global [%0], [%1], 16;" :: "r"(d), "l"(s));
        }
        asm volatile("cp.async.commit_group;");
    };
    auto issue_v = [&](int kt) {
#pragma unroll
        for (int i = 0; i < 8; i++) {
            const int f = tid + 128 * i;
            const int r = f >> 4, c4 = (f & 15) << 2;
            const uint32_t d = sVs + (uint32_t)((r * QSTR + c4) * 4);
            const float* s = Vg + (size_t)r * SEQ + kt * 64 + c4;
            asm volatile("cp.async.cg.shared.global [%0], [%1], 16;" :: "r"(d), "l"(s));
        }
        asm volatile("cp.async.commit_group;");
    };

    issue_k(0);
    issue_v(0);

#pragma unroll
    for (int i = 0; i < 8; i++) {
        const int f = tid + 128 * i;
        const int r = f >> 4, c4 = (f & 15) << 2;
        *(float4*)&Qs[r * QSTR + c4] = *(const float4*)&Qg[r * HD + c4];
    }
    __syncthreads();

    const int rA = warp * 16 + g;

    unsigned qf[8][4];
#pragma unroll
    for (int ks = 0; ks < 8; ks++) {
        const int k0 = ks * 8;
        qf[ks][0] = F2U(Qs[rA * QSTR + k0 + q]);
        qf[ks][1] = F2U(Qs[(rA + 8) * QSTR + k0 + q]);
        qf[ks][2] = F2U(Qs[rA * QSTR + k0 + 4 + q]);
        qf[ks][3] = F2U(Qs[(rA + 8) * QSTR + k0 + 4 + q]);
    }

    const int krow = (lane & 7) + ((lane >> 4) & 1) * 8;
    const int kcol = ((lane >> 3) & 1) * 4;
    const uint32_t kf4 = sKs + (uint32_t)((krow * QSTR + kcol) * 4);
    const uint32_t vf4 = sVs + (uint32_t)((krow * QSTR + kcol) * 4);

    const int ps0 = (lane & ~3) | (q >> 1);
    const int ps2 = ps0 + 2;
    const bool podd = (q & 1);

    float m_i[2], l_i[2], o_acc[8][4];
#pragma unroll
    for (int rh = 0; rh < 2; rh++) { m_i[rh] = -INFINITY; l_i[rh] = 0.0f; }
#pragma unroll
    for (int nt = 0; nt < 8; nt++)
#pragma unroll
        for (int j = 0; j < 4; j++) o_acc[nt][j] = 0.0f;

    for (int kt = 0; kt <= qb; kt++) {
        asm volatile("cp.async.wait_group 1;");
        __syncthreads();

        float s_acc[8][4];
#pragma unroll
        for (int nt = 0; nt < 8; nt++)
#pragma unroll
            for (int j = 0; j < 4; j++) s_acc[nt][j] = 0.0f;

#pragma unroll
        for (int ks = 0; ks < 8; ks++) {
#pragma unroll
            for (int ntp = 0; ntp < 4; ntp++) {
                unsigned b0, b1, b2, b3;
                ldsm4(b0, b1, b2, b3, kf4 + (uint32_t)((ntp * 16 * QSTR + ks * 8) * 4));
                mma8(s_acc[2 * ntp],     qf[ks][0], qf[ks][1], qf[ks][2], qf[ks][3], b0, b1);
                mma8(s_acc[2 * ntp + 1], qf[ks][0], qf[ks][1], qf[ks][2], qf[ks][3], b2, b3);
            }
        }

        const bool diag = (kt == qb);

#pragma unroll
        for (int rh = 0; rh < 2; rh++) {
            const int rg = qb * 64 + rA + rh * 8;
            float mx = -INFINITY;
#pragma unroll
            for (int nt = 0; nt < 8; nt++) {
#pragma unroll
                for (int j = 0; j < 2; j++) {
                    float sv = s_acc[nt][rh * 2 + j];
                    if (diag) {
                        int cg = kt * 64 + nt * 8 + (q << 1) + j;
                        if (cg > rg) sv = -INFINITY;
                    }
                    s_acc[nt][rh * 2 + j] = sv;
                    mx = fmaxf(mx, sv);
                }
            }
            mx = fmaxf(mx, __shfl_xor_sync(0xffffffffu, mx, 1));
            mx = fmaxf(mx, __shfl_xor_sync(0xffffffffu, mx, 2));

            const float mnew = fmaxf(m_i[rh], mx);
            const float sc = __expf(m_i[rh] - mnew);
            m_i[rh] = mnew;

            float rs = 0.0f;
#pragma unroll
            for (int nt = 0; nt < 8; nt++) {
#pragma unroll
                for (int j = 0; j < 2; j++) {
                    float p = __expf(s_acc[nt][rh * 2 + j] - mnew);
                    s_acc[nt][rh * 2 + j] = p;
                    rs += p;
                }
            }
            rs += __shfl_xor_sync(0xffffffffu, rs, 1);
            rs += __shfl_xor_sync(0xffffffffu, rs, 2);

            l_i[rh] = l_i[rh] * sc + rs;
#pragma unroll
            for (int nt = 0; nt < 8; nt++) {
                o_acc[nt][rh * 2]     *= sc;
                o_acc[nt][rh * 2 + 1] *= sc;
            }
        }

        asm volatile("cp.async.wait_group 0;");
        __syncthreads();
        if (kt < qb) issue_k(kt + 1);

#pragma unroll
        for (int ks = 0; ks < 8; ks++) {
            const float t00 = __shfl_sync(0xffffffffu, s_acc[ks][0], ps0);
            const float t01 = __shfl_sync(0xffffffffu, s_acc[ks][1], ps0);
            const float t10 = __shfl_sync(0xffffffffu, s_acc[ks][2], ps0);
            const float t11 = __shfl_sync(0xffffffffu, s_acc[ks][3], ps0);
            const float u00 = __shfl_sync(0xffffffffu, s_acc[ks][0], ps2);
            const float u01 = __shfl_sync(0xffffffffu, s_acc[ks][1], ps2);
            const float u10 = __shfl_sync(0xffffffffu, s_acc[ks][2], ps2);
            const float u11 = __shfl_sync(0xffffffffu, s_acc[ks][3], ps2);
            const unsigned a0 = F2U(tf32r(podd ? t01 : t00));
            const unsigned a1 = F2U(tf32r(podd ? t11 : t10));
            const unsigned a2 = F2U(tf32r(podd ? u01 : u00));
            const unsigned a3 = F2U(tf32r(podd ? u11 : u10));
#pragma unroll
            for (int ntp = 0; ntp < 4; ntp++) {
                unsigned b0, b1, b2, b3;
                ldsm4(b0, b1, b2, b3, vf4 + (uint32_t)((ntp * 16 * QSTR + ks * 8) * 4));
                mma8(o_acc[2 * ntp],     a0, a1, a2, a3, b0, b1);
                mma8(o_acc[2 * ntp + 1], a0, a1, a2, a3, b2, b3);
            }
        }
        __syncthreads();
        if (kt < qb) issue_v(kt + 1);
    }

    const float inv0 = 1.0f / l_i[0];
    const float inv1 = 1.0f / l_i[1];
#pragma unroll
    for (int nt = 0; nt < 8; nt++) {
        const int c = nt * 8 + (q << 1);
        const int r0 = qb * 64 + rA;
        float* p0 = O + ((size_t)b * SEQ + r0) * (NH * HD) + h * HD + c;
        p0[0] = tf32r(o_acc[nt][0] * inv0);
        p0[1] = tf32r(o_acc[nt][1] * inv0);
        float* p1 = O + ((size_t)b * SEQ + r0 + 8) * (NH * HD) + h * HD + c;
        p1[0] = tf32r(o_acc[nt][2] * inv1);
        p1[1] = tf32r(o_acc[nt][3] * inv1);
    }
}

// ---------------------------------------------------------------------------
// kernel_launch
// ---------------------------------------------------------------------------
extern "C" void kernel_launch(void* const* d_in, const int* in_sizes, int n_in,
                              void* d_out, int out_size)
{
    const float* hidden = (const float*)d_in[0];
    const float* wq = (const float*)d_in[1];
    const float* wk = (const float*)d_in[2];
    const float* wv = (const float*)d_in[3];
    const float* wo = (const float*)d_in[4];
    float* out = (float*)d_out;

    float *pq, *pk, *pv, *pattn;
    cudaGetSymbolAddress((void**)&pq, g_q);
    cudaGetSymbolAddress((void**)&pk, g_k);
    cudaGetSymbolAddress((void**)&pv, g_v);
    cudaGetSymbolAddress((void**)&pattn, g_attn);

    const int M = BSZ * SEQ;   // 4096

    cudaFuncSetAttribute(qkv_gemm, cudaFuncAttributeMaxDynamicSharedMemorySize, GEMM_SMEM);
    cudaFuncSetAttribute(gemm_o, cudaFuncAttributeMaxDynamicSharedMemorySize, GEMM_SMEM);
    cudaFuncSetAttribute(flash_tf32, cudaFuncAttributeMaxDynamicSharedMemorySize, FLASH_SMEM);

    // 1) single prologue launch: weight transposes (+round) and rope table
    prologue_all<<<dim3(HIDDEN / 32, HIDDEN / 32, 5), dim3(32, 8)>>>(wq, wk, wv, wo);

    // 2) fused QKV projection + RoPE (A = raw hidden, rounded on fragments)
    qkv_gemm<<<dim3(24, M / 128), dim3(256), GEMM_SMEM>>>(hidden);

    // 3) flash attention (R12 shape)
    flash_tf32<<<dim3(SEQ / 64, NH, BSZ), dim3(128), FLASH_SMEM>>>(pq, pk, pv, pattn);

    // 4) output projection
    gemm_o<<<dim3(HIDDEN / 128, M / 128), dim3(256), GEMM_SMEM>>>(out);
}

// round 16
// speedup vs baseline: 1.0519x; 1.0138x over previous
#include <cuda_runtime.h>
#include <math.h>
#include <stdint.h>

#define BSZ 2
#define SEQ 2048
#define HIDDEN 2048
#define NH 32
#define NKV 8
#define HD 64
#define NREP 4

// Scratch (static device arrays — no allocation).
__device__ float g_q[BSZ * NH * SEQ * HD];      // [b, h, s, d] tf32-rounded, pre-scaled 1/8
__device__ float g_k[BSZ * NKV * SEQ * HD];     // [b, kvh, s, d] tf32-rounded
__device__ float g_v[BSZ * NKV * HD * SEQ];     // [b, kvh, d, s] (TRANSPOSED) tf32-rounded
__device__ float g_attn[BSZ * SEQ * NH * HD];   // [b, s, h*d] tf32-rounded

__device__ float g_wqt[NH * HD * HIDDEN];       // [N,K] k-major, tf32-rounded
__device__ float g_wkt[NKV * HD * HIDDEN];
__device__ float g_wvt[NKV * HD * HIDDEN];
__device__ float g_wot[HIDDEN * NH * HD];       // [N=2048, K=2048]
__device__ float g_rope[SEQ * 64];              // [s][0:32 cos | 32:64 sin]

// ---------------------------------------------------------------------------
// Helpers
// ---------------------------------------------------------------------------
__device__ __forceinline__ float tf32r(float x) {
    unsigned u;
    asm("cvt.rna.tf32.f32 %0, %1;" : "=r"(u) : "f"(x));
    return __uint_as_float(u);
}
#define F2U __float_as_uint

__device__ __forceinline__ void mma8(float c[4],
                                     unsigned a0, unsigned a1, unsigned a2, unsigned a3,
                                     unsigned b0, unsigned b1) {
    asm volatile(
        "mma.sync.aligned.m16n8k8.row.col.f32.tf32.tf32.f32 "
        "{%0,%1,%2,%3}, {%4,%5,%6,%7}, {%8,%9}, {%0,%1,%2,%3};\n"
        : "+f"(c[0]), "+f"(c[1]), "+f"(c[2]), "+f"(c[3])
        : "r"(a0), "r"(a1), "r"(a2), "r"(a3), "r"(b0), "r"(b1));
}
__device__ __forceinline__ void ldsm4(unsigned& r0, unsigned& r1,
                                      unsigned& r2, unsigned& r3, uint32_t addr) {
    asm volatile("ldmatrix.sync.aligned.m8n8.x4.shared.b16 {%0,%1,%2,%3}, [%4];"
                 : "=r"(r0), "=r"(r1), "=r"(r2), "=r"(r3) : "r"(addr));
}

// ---------------------------------------------------------------------------
// Prologue (single launch, exact 1D grid = 10496 blocks):
//   [0,4096)      wq transpose  (64 x, 64 y)
//   [4096,5120)   wk transpose  (16 x, 64 y)
//   [5120,6144)   wv transpose  (16 x, 64 y)
//   [6144,10240)  wo transpose  (64 x, 64 y)
//   [10240,10496) rope table
// ---------------------------------------------------------------------------
#define PRO_BLOCKS 10496

__global__ void prologue_all(const float* __restrict__ wq, const float* __restrict__ wk,
                             const float* __restrict__ wv, const float* __restrict__ wo)
{
    __shared__ float t[32][33];
    const int id = blockIdx.x;
    const int tx = threadIdx.x, ty = threadIdx.y;

    if (id >= 10240) {
        const int idx = (id - 10240) * 256 + ty * 32 + tx;
        const int s = idx >> 5, p = idx & 31;
        float inv = powf(10000.0f, -((float)(2 * p) / 64.0f));
        float ang = (float)s * inv;
        float c, si;
        sincosf(ang, &si, &c);
        g_rope[s * 64 + p] = c;
        g_rope[s * 64 + 32 + p] = si;
        return;
    }

    const float* src;
    float* dst;
    int Kd, Nd, n0, k0;
    if (id < 4096)      { src = wq; dst = g_wqt; Kd = HIDDEN;  Nd = NH * HD;
                          n0 = (id & 63) * 32;          k0 = (id >> 6) * 32; }
    else if (id < 5120) { src = wk; dst = g_wkt; Kd = HIDDEN;  Nd = NKV * HD;
                          n0 = ((id - 4096) & 15) * 32; k0 = ((id - 4096) >> 4) * 32; }
    else if (id < 6144) { src = wv; dst = g_wvt; Kd = HIDDEN;  Nd = NKV * HD;
                          n0 = ((id - 5120) & 15) * 32; k0 = ((id - 5120) >> 4) * 32; }
    else                { src = wo; dst = g_wot; Kd = NH * HD; Nd = HIDDEN;
                          n0 = ((id - 6144) & 63) * 32; k0 = ((id - 6144) >> 6) * 32; }

#pragma unroll
    for (int i = 0; i < 4; i++)
        t[ty + i * 8][tx] = src[(size_t)(k0 + ty + i * 8) * Nd + n0 + tx];
    __syncthreads();
#pragma unroll
    for (int i = 0; i < 4; i++)
        dst[(size_t)(n0 + ty + i * 8) * Kd + k0 + tx] = tf32r(t[tx][ty + i * 8]);
}

// ---------------------------------------------------------------------------
// GEMM mainloop v3 (R12 schedule): 128x128 tile, BK=32, 3-stage cp.async,
// XOR-swizzled smem, both fragments via ldmatrix.
// CVT_A: apply tf32 rounding to A fragments after ldsm (A source is raw fp32).
// ---------------------------------------------------------------------------
#define STAGE_B 16384u
#define GEMM_SMEM (6 * 16384)

template<int WARPS_M, bool CVT_A>
__device__ __forceinline__ void gemm_mainloop3(
    const float* __restrict__ Ag, const float* __restrict__ Bg,
    int K, float (*acc)[4])
{
    extern __shared__ float smem[];
    constexpr int MT = 8 / WARPS_M;
    constexpr int NT = 2 * WARPS_M;
    constexpr int NPAIR = NT / 2;

    const int tid  = threadIdx.x;
    const int lane = tid & 31;
    const int warp = tid >> 5;
    const int wm   = warp % WARPS_M;
    const int wn   = warp / WARPS_M;

    const uint32_t sA = (uint32_t)__cvta_generic_to_shared(smem);
    const uint32_t sB = sA + 3 * STAGE_B;

    const int lrow = tid >> 3;
    const int lj   = tid & 7;
    const uint32_t wsw = (uint32_t)((lj ^ (lrow & 7)) << 4);

    const int frow = ((lane >> 3) & 1) * 8 + (lane & 7);
    const int fjb  = lane >> 4;
    const int axr  = frow & 7;
    const uint32_t arowb = (uint32_t)((wm * MT * 16 + frow) * 128);
    const int brow = (lane & 7) + ((lane >> 4) & 1) * 8;
    const int bjb  = (lane >> 3) & 1;
    const int bxr  = brow & 7;
    const uint32_t browb = (uint32_t)((wn * NT * 8 + brow) * 128);

#define ISSUE(kc, st) do {                                                           \
    _Pragma("unroll")                                                                \
    for (int i = 0; i < 4; i++) {                                                    \
        const int r = lrow + 32 * i;                                                 \
        const float* sa = Ag + (size_t)r * K + (kc) * 32 + lj * 4;                   \
        const uint32_t da = sA + (uint32_t)(st) * STAGE_B + (uint32_t)(r * 128) + wsw; \
        asm volatile("cp.async.cg.shared.global [%0], [%1], 16;" :: "r"(da), "l"(sa)); \
    }                                                                                \
    _Pragma("unroll")                                                                \
    for (int i = 0; i < 4; i++) {                                                    \
        const int r = lrow + 32 * i;                                                 \
        const float* sb = Bg + (size_t)r * K + (kc) * 32 + lj * 4;                   \
        const uint32_t db = sB + (uint32_t)(st) * STAGE_B + (uint32_t)(r * 128) + wsw; \
        asm volatile("cp.async.cg.shared.global [%0], [%1], 16;" :: "r"(db), "l"(sb)); \
    }                                                                                \
    asm volatile("cp.async.commit_group;");                                          \
} while (0)

    const int nkc = K >> 5;
    ISSUE(0, 0);
    ISSUE(1, 1);

    for (int kc = 0; kc < nkc; kc++) {
        if (kc < nkc - 1) asm volatile("cp.async.wait_group 1;");
        else              asm volatile("cp.async.wait_group 0;");
        __syncthreads();

        const int st = kc % 3;
        const uint32_t aS = sA + (uint32_t)st * STAGE_B;
        const uint32_t bS = sB + (uint32_t)st * STAGE_B;

#pragma unroll
        for (int ks = 0; ks < 4; ks++) {
            unsigned a[MT][4];
#pragma unroll
            for (int mt = 0; mt < MT; mt++) {
                ldsm4(a[mt][0], a[mt][1], a[mt][2], a[mt][3],
                      aS + arowb + (uint32_t)(mt * 2048)
                         + (uint32_t)((((2 * ks + fjb) ^ axr)) << 4));
                if (CVT_A) {
#pragma unroll
                    for (int j = 0; j < 4; j++)
                        a[mt][j] = F2U(tf32r(__uint_as_float(a[mt][j])));
                }
            }
#pragma unroll
            for (int ntp = 0; ntp < NPAIR; ntp++) {
                unsigned b0, b1, b2, b3;
                ldsm4(b0, b1, b2, b3,
                      bS + browb + (uint32_t)(ntp * 2048)
                         + (uint32_t)((((2 * ks + bjb) ^ bxr)) << 4));
#pragma unroll
                for (int mt = 0; mt < MT; mt++) {
                    mma8(acc[mt * NT + 2 * ntp],     a[mt][0], a[mt][1], a[mt][2], a[mt][3], b0, b1);
                    mma8(acc[mt * NT + 2 * ntp + 1], a[mt][0], a[mt][1], a[mt][2], a[mt][3], b2, b3);
                }
            }
        }
        if (kc + 2 < nkc) ISSUE(kc + 2, (kc + 2) % 3);
    }
#undef ISSUE
}

// ---------------------------------------------------------------------------
// Fused QKV projection + RoPE epilogue (cos/sin from g_rope table).
// A = raw hidden (tf32-rounded on fragments). V stored TRANSPOSED [b,kvh,d,s].
// ---------------------------------------------------------------------------
__global__ __launch_bounds__(256, 2)
void qkv_gemm(const float* __restrict__ hidden)
{
    const int bx = blockIdx.x, by = blockIdx.y;
    const int tid = threadIdx.x;
    const int lane = tid & 31, warp = tid >> 5;
    const int wm = warp % 4, wn = warp / 4;
    const int q = lane & 3, g = lane >> 2;

    const float* W;
    float* Out;
    int cb, heads;
    bool rope;
    float oscale;
    if (bx < 16)      { W = g_wqt; Out = g_q; cb = bx * 128;        heads = NH;  rope = true;  oscale = 0.125f; }
    else if (bx < 20) { W = g_wkt; Out = g_k; cb = (bx - 16) * 128; heads = NKV; rope = true;  oscale = 1.0f; }
    else              { W = g_wvt; Out = g_v; cb = (bx - 20) * 128; heads = NKV; rope = false; oscale = 1.0f; }

    float acc[16][4];
#pragma unroll
    for (int i = 0; i < 16; i++)
#pragma unroll
        for (int j = 0; j < 4; j++) acc[i][j] = 0.0f;

    gemm_mainloop3<4, true>(hidden + (size_t)(by * 128) * HIDDEN,
                            W + (size_t)cb * HIDDEN, HIDDEN, acc);

    if (rope) {
#pragma unroll
        for (int mt = 0; mt < 2; mt++) {
#pragma unroll
            for (int rh = 0; rh < 2; rh++) {
                const int m = by * 128 + wm * 32 + mt * 16 + g + rh * 8;
                const int ss = m & (SEQ - 1);
                const float* rp = g_rope + ss * 64;
#pragma unroll
                for (int ntp = 0; ntp < 4; ntp++) {
                    const int f = ntp * 8 + (q << 1);
                    const float2 cc = *(const float2*)(rp + f);
                    const float2 sn = *(const float2*)(rp + 32 + f);
                    {
                        const float x1 = acc[mt * 8 + ntp][rh * 2];
                        const float x2 = acc[mt * 8 + ntp + 4][rh * 2];
                        acc[mt * 8 + ntp][rh * 2]     = x1 * cc.x - x2 * sn.x;
                        acc[mt * 8 + ntp + 4][rh * 2] = x2 * cc.x + x1 * sn.x;
                    }
                    {
                        const float x1 = acc[mt * 8 + ntp][rh * 2 + 1];
                        const float x2 = acc[mt * 8 + ntp + 4][rh * 2 + 1];
                        acc[mt * 8 + ntp][rh * 2 + 1]     = x1 * cc.y - x2 * sn.y;
                        acc[mt * 8 + ntp + 4][rh * 2 + 1] = x2 * cc.y + x1 * sn.y;
                    }
                }
            }
        }
    }

#pragma unroll
    for (int mt = 0; mt < 2; mt++) {
        const int row = by * 128 + wm * 32 + mt * 16 + g;
#pragma unroll
        for (int nt = 0; nt < 8; nt++) {
            const int col = cb + wn * 64 + nt * 8 + (q << 1);
            const int hh = col / HD, dd = col & (HD - 1);
#pragma unroll
            for (int rh = 0; rh < 2; rh++) {
                const int m = row + rh * 8;
                const int bb = m >> 11, ss = m & (SEQ - 1);
                if (rope) {
                    float* p = Out + (((size_t)bb * heads + hh) * SEQ + ss) * HD + dd;
                    p[0] = tf32r(acc[mt * 8 + nt][rh * 2]     * oscale);
                    p[1] = tf32r(acc[mt * 8 + nt][rh * 2 + 1] * oscale);
                } else {
                    float* p = Out + (((size_t)bb * heads + hh) * HD + dd) * SEQ + ss;
                    p[0]   = tf32r(acc[mt * 8 + nt][rh * 2]);
                    p[SEQ] = tf32r(acc[mt * 8 + nt][rh * 2 + 1]);
                }
            }
        }
    }
}

// ---------------------------------------------------------------------------
// Output projection
// ---------------------------------------------------------------------------
__global__ __launch_bounds__(256, 2)
void gemm_o(float* __restrict__ C)
{
    const int bx = blockIdx.x, by = blockIdx.y;
    const int tid = threadIdx.x;
    const int lane = tid & 31, warp = tid >> 5;
    const int wm = warp % 2, wn = warp / 2;
    const int q = lane & 3, g = lane >> 2;

    float acc[16][4];
#pragma unroll
    for (int i = 0; i < 16; i++)
#pragma unroll
        for (int j = 0; j < 4; j++) acc[i][j] = 0.0f;

    gemm_mainloop3<2, false>(g_attn + (size_t)(by * 128) * HIDDEN,
                             g_wot + (size_t)(bx * 128) * HIDDEN, HIDDEN, acc);

#pragma unroll
    for (int mt = 0; mt < 4; mt++) {
        const int row = by * 128 + wm * 64 + mt * 16 + g;
#pragma unroll
        for (int nt = 0; nt < 4; nt++) {
            const int col = bx * 128 + wn * 32 + nt * 8 + (q << 1);
            *(float2*)(C + (size_t)row * HIDDEN + col) =
                make_float2(acc[mt * 4 + nt][0], acc[mt * 4 + nt][1]);
            *(float2*)(C + (size_t)(row + 8) * HIDDEN + col) =
                make_float2(acc[mt * 4 + nt][2], acc[mt * 4 + nt][3]);
        }
    }
}

// ---------------------------------------------------------------------------
// Flash attention (R12 shape + diag specialization): 64-row Q tiles, 4 warps,
// occ 3, cp.async K/V alternating pipeline, shuffle-resident P.
// Main loop (kt < qb): mask-free. Diag tile (kt == qb): warp w computes only
// S n-tiles ntp <= w and PV k-slabs ks <= 2w+1 (the rest are exact zeros).
// ---------------------------------------------------------------------------
#define QSTR 68
#define FLASH_SMEM ((64 * QSTR * 3) * 4)

__global__ __launch_bounds__(128, 3)
void flash_tf32(const float* __restrict__ Q, const float* __restrict__ K,
                const float* __restrict__ V, float* __restrict__ O)
{
    extern __shared__ float sm[];
    float* Qs = sm;
    float* Ks = Qs + 64 * QSTR;
    float* Vs = Ks + 64 * QSTR;       // [64 d][QSTR] (transposed V tile)

    const int qb   = gridDim.x - 1 - blockIdx.x;   // heavy blocks first
    const int h    = blockIdx.y;
    const int b    = blockIdx.z;
    const int tid  = threadIdx.x;
    const int lane = tid & 31;
    const int warp = tid >> 5;
    const int q    = lane & 3;
    const int g    = lane >> 2;

    const float* Qg = Q + (((size_t)b * NH + h) * SEQ + qb * 64) * HD;
    const float* Kg = K + ((size_t)b * NKV + h / NREP) * SEQ * HD;
    const float* Vg = V + ((size_t)b * NKV + h / NREP) * HD * SEQ;  // [d][s]

    const uint32_t sKs = (uint32_t)__cvta_generic_to_shared(Ks);
    const uint32_t sVs = (uint32_t)__cvta_generic_to_shared(Vs);

    auto issue_k = [&](int kt) {
#pragma unroll
        for (int i = 0; i < 8; i++) {
            const int f = tid + 128 * i;
            const int r = f >> 4, c4 = (f & 15) << 2;
            const uint32_t d = sKs + (uint32_t)((r * QSTR + c4) * 4);
            const float* s = Kg + (size_t)kt * 64 * HD + f * 4;
            asm volatile("cp.async.cg.shared.global [%0], [%1], 16;" :: "r"(d), "l"(s));
        }
        asm volatile("cp.async.commit_group;");
    };
    auto issue_v = [&](int kt) {
#pragma unroll
        for (int i = 0; i < 8; i++) {
            const int f = tid + 128 * i;
            const int r = f >> 4, c4 = (f & 15) << 2;
            const uint32_t d = sVs + (uint32_t)((r * QSTR + c4) * 4);
            const float* s = Vg + (size_t)r * SEQ + kt * 64 + c4;
            asm volatile("cp.async.cg.shared.global [%0], [%1], 16;" :: "r"(d), "l"(s));
        }
        asm volatile("cp.async.commit_group;");
    };

    issue_k(0);
    issue_v(0);

#pragma unroll
    for (int i = 0; i < 8; i++) {
        const int f = tid + 128 * i;
        const int r = f >> 4, c4 = (f & 15) << 2;
        *(float4*)&Qs[r * QSTR + c4] = *(const float4*)&Qg[r * HD + c4];
    }
    __syncthreads();

    const int rA = warp * 16 + g;

    unsigned qf[8][4];
#pragma unroll
    for (int ks = 0; ks < 8; ks++) {
        const int k0 = ks * 8;
        qf[ks][0] = F2U(Qs[rA * QSTR + k0 + q]);
        qf[ks][1] = F2U(Qs[(rA + 8) * QSTR + k0 + q]);
        qf[ks][2] = F2U(Qs[rA * QSTR + k0 + 4 + q]);
        qf[ks][3] = F2U(Qs[(rA + 8) * QSTR + k0 + 4 + q]);
    }

    const int krow = (lane & 7) + ((lane >> 4) & 1) * 8;
    const int kcol = ((lane >> 3) & 1) * 4;
    const uint32_t kf4 = sKs + (uint32_t)((krow * QSTR + kcol) * 4);
    const uint32_t vf4 = sVs + (uint32_t)((krow * QSTR + kcol) * 4);

    const int ps0 = (lane & ~3) | (q >> 1);
    const int ps2 = ps0 + 2;
    const bool podd = (q & 1);

    float m_i[2], l_i[2], o_acc[8][4];
#pragma unroll
    for (int rh = 0; rh < 2; rh++) { m_i[rh] = -INFINITY; l_i[rh] = 0.0f; }
#pragma unroll
    for (int nt = 0; nt < 8; nt++)
#pragma unroll
        for (int j = 0; j < 4; j++) o_acc[nt][j] = 0.0f;

    float s_acc[8][4];

    // ---- softmax + rescale, shared by main/diag (diag: pre-masked s_acc) ----
    auto softmax_update = [&]() {
#pragma unroll
        for (int rh = 0; rh < 2; rh++) {
            float mx = -INFINITY;
#pragma unroll
            for (int nt = 0; nt < 8; nt++) {
                mx = fmaxf(mx, s_acc[nt][rh * 2]);
                mx = fmaxf(mx, s_acc[nt][rh * 2 + 1]);
            }
            mx = fmaxf(mx, __shfl_xor_sync(0xffffffffu, mx, 1));
            mx = fmaxf(mx, __shfl_xor_sync(0xffffffffu, mx, 2));

            const float mnew = fmaxf(m_i[rh], mx);
            const float sc = __expf(m_i[rh] - mnew);
            m_i[rh] = mnew;

            float rs = 0.0f;
#pragma unroll
            for (int nt = 0; nt < 8; nt++) {
#pragma unroll
                for (int j = 0; j < 2; j++) {
                    float p = __expf(s_acc[nt][rh * 2 + j] - mnew);
                    s_acc[nt][rh * 2 + j] = p;
                    rs += p;
                }
            }
            rs += __shfl_xor_sync(0xffffffffu, rs, 1);
            rs += __shfl_xor_sync(0xffffffffu, rs, 2);

            l_i[rh] = l_i[rh] * sc + rs;
#pragma unroll
            for (int nt = 0; nt < 8; nt++) {
                o_acc[nt][rh * 2]     *= sc;
                o_acc[nt][rh * 2 + 1] *= sc;
            }
        }
    };

    // ---------------- main loop: kt < qb, mask-free ----------------
    for (int kt = 0; kt < qb; kt++) {
        asm volatile("cp.async.wait_group 1;");
        __syncthreads();

#pragma unroll
        for (int nt = 0; nt < 8; nt++)
#pragma unroll
            for (int j = 0; j < 4; j++) s_acc[nt][j] = 0.0f;

#pragma unroll
        for (int ks = 0; ks < 8; ks++) {
#pragma unroll
            for (int ntp = 0; ntp < 4; ntp++) {
                unsigned b0, b1, b2, b3;
                ldsm4(b0, b1, b2, b3, kf4 + (uint32_t)((ntp * 16 * QSTR + ks * 8) * 4));
                mma8(s_acc[2 * ntp],     qf[ks][0], qf[ks][1], qf[ks][2], qf[ks][3], b0, b1);
                mma8(s_acc[2 * ntp + 1], qf[ks][0], qf[ks][1], qf[ks][2], qf[ks][3], b2, b3);
            }
        }

        softmax_update();

        asm volatile("cp.async.wait_group 0;");
        __syncthreads();
        issue_k(kt + 1);

#pragma unroll
        for (int ks = 0; ks < 8; ks++) {
            const float t00 = __shfl_sync(0xffffffffu, s_acc[ks][0], ps0);
            const float t01 = __shfl_sync(0xffffffffu, s_acc[ks][1], ps0);
            const float t10 = __shfl_sync(0xffffffffu, s_acc[ks][2], ps0);
            const float t11 = __shfl_sync(0xffffffffu, s_acc[ks][3], ps0);
            const float u00 = __shfl_sync(0xffffffffu, s_acc[ks][0], ps2);
            const float u01 = __shfl_sync(0xffffffffu, s_acc[ks][1], ps2);
            const float u10 = __shfl_sync(0xffffffffu, s_acc[ks][2], ps2);
            const float u11 = __shfl_sync(0xffffffffu, s_acc[ks][3], ps2);
            const unsigned a0 = F2U(tf32r(podd ? t01 : t00));
            const unsigned a1 = F2U(tf32r(podd ? t11 : t10));
            const unsigned a2 = F2U(tf32r(podd ? u01 : u00));
            const unsigned a3 = F2U(tf32r(podd ? u11 : u10));
#pragma unroll
            for (int ntp = 0; ntp < 4; ntp++) {
                unsigned b0, b1, b2, b3;
                ldsm4(b0, b1, b2, b3, vf4 + (uint32_t)((ntp * 16 * QSTR + ks * 8) * 4));
                mma8(o_acc[2 * ntp],     a0, a1, a2, a3, b0, b1);
                mma8(o_acc[2 * ntp + 1], a0, a1, a2, a3, b2, b3);
            }
        }
        __syncthreads();
        issue_v(kt + 1);
    }

    // ---------------- diag tile: kt == qb ----------------
    {
        const int kt = qb;
        asm volatile("cp.async.wait_group 1;");
        __syncthreads();

        // only ntp <= warp contains unmasked keys for this warp's rows
#pragma unroll
        for (int nt = 0; nt < 8; nt++)
#pragma unroll
            for (int j = 0; j < 4; j++) s_acc[nt][j] = 0.0f;

#pragma unroll
        for (int ks = 0; ks < 8; ks++) {
#pragma unroll
            for (int ntp = 0; ntp < 4; ntp++) {
                if (ntp > warp) break;
                unsigned b0, b1, b2, b3;
                ldsm4(b0, b1, b2, b3, kf4 + (uint32_t)((ntp * 16 * QSTR + ks * 8) * 4));
                mma8(s_acc[2 * ntp],     qf[ks][0], qf[ks][1], qf[ks][2], qf[ks][3], b0, b1);
                mma8(s_acc[2 * ntp + 1], qf[ks][0], qf[ks][1], qf[ks][2], qf[ks][3], b2, b3);
            }
        }

        // causal mask (applies -inf to all keys > row, incl. skipped n-tiles)
#pragma unroll
        for (int rh = 0; rh < 2; rh++) {
            const int rg = qb * 64 + rA + rh * 8;
#pragma unroll
            for (int nt = 0; nt < 8; nt++) {
#pragma unroll
                for (int j = 0; j < 2; j++) {
                    const int cg = kt * 64 + nt * 8 + (q << 1) + j;
                    if (cg > rg) s_acc[nt][rh * 2 + j] = -INFINITY;
                }
            }
        }

        softmax_update();

        asm volatile("cp.async.wait_group 0;");
        __syncthreads();

        // PV: only key slabs ks <= 2*warp+1 have nonzero P for this warp
#pragma unroll
        for (int ks = 0; ks < 8; ks++) {
            if (ks > 2 * warp + 1) break;
            const float t00 = __shfl_sync(0xffffffffu, s_acc[ks][0], ps0);
            const float t01 = __shfl_sync(0xffffffffu, s_acc[ks][1], ps0);
            const float t10 = __shfl_sync(0xffffffffu, s_acc[ks][2], ps0);
            const float t11 = __shfl_sync(0xffffffffu, s_acc[ks][3], ps0);
            const float u00 = __shfl_sync(0xffffffffu, s_acc[ks][0], ps2);
            const float u01 = __shfl_sync(0xffffffffu, s_acc[ks][1], ps2);
            const float u10 = __shfl_sync(0xffffffffu, s_acc[ks][2], ps2);
            const float u11 = __shfl_sync(0xffffffffu, s_acc[ks][3], ps2);
            const unsigned a0 = F2U(tf32r(podd ? t01 : t00));
            const unsigned a1 = F2U(tf32r(podd ? t11 : t10));
            const unsigned a2 = F2U(tf32r(podd ? u01 : u00));
            const unsigned a3 = F2U(tf32r(podd ? u11 : u10));
#pragma unroll
            for (int ntp = 0; ntp < 4; ntp++) {
                unsigned b0, b1, b2, b3;
                ldsm4(b0, b1, b2, b3, vf4 + (uint32_t)((ntp * 16 * QSTR + ks * 8) * 4));
                mma8(o_acc[2 * ntp],     a0, a1, a2, a3, b0, b1);
                mma8(o_acc[2 * ntp + 1], a0, a1, a2, a3, b2, b3);
            }
        }
    }

    const float inv0 = 1.0f / l_i[0];
    const float inv1 = 1.0f / l_i[1];
#pragma unroll
    for (int nt = 0; nt < 8; nt++) {
        const int c = nt * 8 + (q << 1);
        const int r0 = qb * 64 + rA;
        float* p0 = O + ((size_t)b * SEQ + r0) * (NH * HD) + h * HD + c;
        p0[0] = tf32r(o_acc[nt][0] * inv0);
        p0[1] = tf32r(o_acc[nt][1] * inv0);
        float* p1 = O + ((size_t)b * SEQ + r0 + 8) * (NH * HD) + h * HD + c;
        p1[0] = tf32r(o_acc[nt][2] * inv1);
        p1[1] = tf32r(o_acc[nt][3] * inv1);
    }
}

// ---------------------------------------------------------------------------
// kernel_launch
// ---------------------------------------------------------------------------
extern "C" void kernel_launch(void* const* d_in, const int* in_sizes, int n_in,
                              void* d_out, int out_size)
{
    const float* hidden = (const float*)d_in[0];
    const float* wq = (const float*)d_in[1];
    const float* wk = (const float*)d_in[2];
    const float* wv = (const float*)d_in[3];
    const float* wo = (const float*)d_in[4];
    float* out = (float*)d_out;

    float *pq, *pk, *pv, *pattn;
    cudaGetSymbolAddress((void**)&pq, g_q);
    cudaGetSymbolAddress((void**)&pk, g_k);
    cudaGetSymbolAddress((void**)&pv, g_v);
    cudaGetSymbolAddress((void**)&pattn, g_attn);

    const int M = BSZ * SEQ;   // 4096

    cudaFuncSetAttribute(qkv_gemm, cudaFuncAttributeMaxDynamicSharedMemorySize, GEMM_SMEM);
    cudaFuncSetAttribute(gemm_o, cudaFuncAttributeMaxDynamicSharedMemorySize, GEMM_SMEM);
    cudaFuncSetAttribute(flash_tf32, cudaFuncAttributeMaxDynamicSharedMemorySize, FLASH_SMEM);

    // 1) single prologue launch (exact grid): weight transposes + rope table
    prologue_all<<<PRO_BLOCKS, dim3(32, 8)>>>(wq, wk, wv, wo);

    // 2) fused QKV projection + RoPE
    qkv_gemm<<<dim3(24, M / 128), dim3(256), GEMM_SMEM>>>(hidden);

    // 3) flash attention (diag-specialized)
    flash_tf32<<<dim3(SEQ / 64, NH, BSZ), dim3(128), FLASH_SMEM>>>(pq, pk, pv, pattn);

    // 4) output projection
    gemm_o<<<dim3(HIDDEN / 128, M / 128), dim3(256), GEMM_SMEM>>>(out);
}